// round 11
// baseline (speedup 1.0000x reference)
#include <cuda_runtime.h>
#include <cuda_fp16.h>
#include <cstdint>

// ---------------------------------------------------------------------------
// LinearAttention, fp16 mma.sync m16n8k16 (fp32 accum) + ldmatrix.
// R11: global->shared staging via cp.async.bulk row copies + mbarrier
// (160 issue slots/stage instead of 1024 LDGSTS — the R6 profile showed the
// LDGSTS issue rate, not the tensor pipe, was the binding constraint).
// ---------------------------------------------------------------------------

#define BDIM   8
#define CIN    256
#define NPIX   4096
#define HEADS  4
#define DIMH   128
#define HID    512
#define QKVR   1536
#define KSPLIT 8

#define SAH    40                 // A smem stride (halfs): 80B (16B-aligned)
#define SBH    136                // B smem stride (halfs): 272B (16B-aligned)
#define ASTGH  (128 * SAH)        // 5120 halfs
#define BSTGH  (32 * SBH)         // 4352 halfs
#define SMEM_NN (32 + 3 * (ASTGH + BSTGH) * 2)   // 56864
#define SMEM_NT (32 + 3 * 2 * ASTGH * 2)         // 61472
#define STG_BYTES 16384           // bytes per stage (A 8192 + B 8192), all kernels

__device__ __half g_qkvh[(size_t)BDIM * QKVR * NPIX];
__device__ __half g_attnh[(size_t)BDIM * HID * NPIX];
__device__ float  g_ctx_part[KSPLIT][BDIM * HEADS][DIMH][DIMH];
__device__ __half g_ctxTh[BDIM * HEADS][DIMH][DIMH];
__device__ __half g_xh [(size_t)BDIM * CIN * NPIX];
__device__ __half g_wqh[QKVR * CIN];
__device__ __half g_woh[CIN * HID];

// ---------------- helpers ----------------
__device__ __forceinline__ void ldsm_x4(uint32_t r[4], uint32_t a) {
    asm volatile("ldmatrix.sync.aligned.m8n8.x4.shared.b16 {%0,%1,%2,%3}, [%4];"
        : "=r"(r[0]), "=r"(r[1]), "=r"(r[2]), "=r"(r[3]) : "r"(a));
}
__device__ __forceinline__ void ldsm_x4t(uint32_t r[4], uint32_t a) {
    asm volatile("ldmatrix.sync.aligned.m8n8.x4.trans.shared.b16 {%0,%1,%2,%3}, [%4];"
        : "=r"(r[0]), "=r"(r[1]), "=r"(r[2]), "=r"(r[3]) : "r"(a));
}
__device__ __forceinline__ void mma16(float c[4], const uint32_t a[4], const uint32_t b0, const uint32_t b1) {
    asm volatile(
        "mma.sync.aligned.m16n8k16.row.col.f32.f16.f16.f32 "
        "{%0,%1,%2,%3}, {%4,%5,%6,%7}, {%8,%9}, {%0,%1,%2,%3};"
        : "+f"(c[0]), "+f"(c[1]), "+f"(c[2]), "+f"(c[3])
        : "r"(a[0]), "r"(a[1]), "r"(a[2]), "r"(a[3]), "r"(b0), "r"(b1));
}
__device__ __forceinline__ void mbar_init(uint32_t a, uint32_t c) {
    asm volatile("mbarrier.init.shared.b64 [%0], %1;" :: "r"(a), "r"(c) : "memory");
}
__device__ __forceinline__ void mbar_expect(uint32_t a, uint32_t bytes) {
    asm volatile("mbarrier.arrive.expect_tx.shared.b64 _, [%0], %1;"
                 :: "r"(a), "r"(bytes) : "memory");
}
__device__ __forceinline__ void mbar_wait(uint32_t a, uint32_t par) {
    uint32_t d;
    asm volatile("{\n\t.reg .pred p;\n\t"
        "mbarrier.try_wait.parity.acquire.cta.shared::cta.b64 p, [%1], %2;\n\t"
        "selp.b32 %0, 1, 0, p;\n\t}" : "=r"(d) : "r"(a), "r"(par) : "memory");
    if (!d) {
        asm volatile("{\n\t.reg .pred P1;\n\t"
            "W_%=:\n\t"
            "mbarrier.try_wait.parity.acquire.cta.shared::cta.b64 P1, [%0], %1, 0x989680;\n\t"
            "@P1 bra.uni D_%=;\n\t"
            "bra.uni W_%=;\n\t"
            "D_%=:\n\t}" :: "r"(a), "r"(par) : "memory");
    }
}
__device__ __forceinline__ void bulk_g2s(uint32_t dst, const void* src,
                                         uint32_t bytes, uint32_t mbar) {
    asm volatile(
        "cp.async.bulk.shared::cta.global.mbarrier::complete_tx::bytes [%0], [%1], %2, [%3];"
        :: "r"(dst), "l"(src), "r"(bytes), "r"(mbar) : "memory");
}

// ---------------------------------------------------------------------------
__global__ __launch_bounds__(256) void f2h(
    const float* __restrict__ in, __half* __restrict__ out, int n4)
{
    int i = blockIdx.x * 256 + threadIdx.x;
    if (i < n4) {
        float4 v = ((const float4*)in)[i];
        __half2 h0 = __floats2half2_rn(v.x, v.y);
        __half2 h1 = __floats2half2_rn(v.z, v.w);
        uint2 u;
        u.x = *(uint32_t*)&h0;
        u.y = *(uint32_t*)&h1;
        ((uint2*)out)[i] = u;
    }
}
__global__ __launch_bounds__(256) void f2h2(
    const float* __restrict__ a, __half* __restrict__ oa, int na4,
    const float* __restrict__ b, __half* __restrict__ ob, int nb4)
{
    int i = blockIdx.x * 256 + threadIdx.x;
    const float* src; __half* dst; int j;
    if (i < na4) { src = a; dst = oa; j = i; }
    else         { j = i - na4; if (j >= nb4) return; src = b; dst = ob; }
    float4 v = ((const float4*)src)[j];
    __half2 h0 = __floats2half2_rn(v.x, v.y);
    __half2 h1 = __floats2half2_rn(v.z, v.w);
    uint2 u;
    u.x = *(uint32_t*)&h0;
    u.y = *(uint32_t*)&h1;
    ((uint2*)dst)[j] = u;
}

// ---------------------------------------------------------------------------
// NN GEMM fp16: C = A[M,K]@B[K,N] (+bias). 128x128 tile, BK=32, 3-stage
// cp.async.bulk + mbarrier pipeline.
// ---------------------------------------------------------------------------
template<bool HALF_OUT>
__global__ __launch_bounds__(256, 2) void gemm_nn(
    const __half* __restrict__ A, long long sA1, long long sA2, int lda,
    const __half* __restrict__ B, long long sB1, long long sB2,
    void*         __restrict__ Cv, long long sC1, long long sC2,
    const float* __restrict__ bias,
    int zdiv, int N, int K)
{
    extern __shared__ __half sm[];
    const uint32_t smb  = (uint32_t)__cvta_generic_to_shared(sm);
    const uint32_t mb   = smb;                 // 3 mbarriers (24B, pad to 32)
    const uint32_t asm0 = smb + 32;
    const uint32_t bsm0 = asm0 + 3 * ASTGH * 2;

    const int bm = blockIdx.y, bn = blockIdx.x;
    const int zo = blockIdx.z / zdiv, zi = blockIdx.z % zdiv;
    A += zo * sA1 + zi * sA2;
    B += zo * sB1 + zi * sB2;

    const int tid  = threadIdx.x;
    const int lane = tid & 31, warp = tid >> 5;
    const int g    = lane >> 2, t4 = lane & 3;
    const int wm   = warp & 3,  wn = warp >> 2;
    const int l15  = lane & 15, lh = lane >> 4;

    const __half* Ag = A + (long long)bm * 128 * lda;
    const __half* Bg = B + bn * 128;

    if (tid == 0) {
        mbar_init(mb, 1); mbar_init(mb + 8, 1); mbar_init(mb + 16, 1);
    }
    __syncthreads();

#define LD_STAGE(st, kk) do {                                                     \
    uint32_t _m = mb + (uint32_t)(st) * 8;                                        \
    if (tid == 0) mbar_expect(_m, STG_BYTES);                                     \
    if (tid < 128) {                                                              \
        bulk_g2s(asm0 + (uint32_t)(st) * (ASTGH * 2) + (uint32_t)tid * (SAH * 2), \
                 Ag + (long long)tid * lda + (kk), 64, _m);                       \
    } else if (tid < 160) {                                                       \
        int kr = tid - 128;                                                       \
        bulk_g2s(bsm0 + (uint32_t)(st) * (BSTGH * 2) + (uint32_t)kr * (SBH * 2),  \
                 Bg + (long long)((kk) + kr) * N, 256, _m);                       \
    }                                                                             \
} while (0)

    float acc[2][8][4] = {};
    const int niter = K >> 5;

    LD_STAGE(0, 0);
    LD_STAGE(1, 32);

    for (int it = 0; it < niter; ++it) {
        mbar_wait(mb + (uint32_t)(it % 3) * 8, (uint32_t)((it / 3) & 1));
        __syncthreads();
        const int ls = it + 2;
        if (ls < niter) LD_STAGE(ls % 3, ls * 32);

        const uint32_t Asb = asm0 + (uint32_t)(it % 3) * (ASTGH * 2);
        const uint32_t Bsb = bsm0 + (uint32_t)(it % 3) * (BSTGH * 2);

#pragma unroll
        for (int k16 = 0; k16 < 32; k16 += 16) {
            uint32_t af[2][4], bf[8][2];
#pragma unroll
            for (int im = 0; im < 2; im++) {
                int m = wm * 32 + im * 16 + l15;
                ldsm_x4(af[im], Asb + (uint32_t)(m * SAH + k16 + lh * 8) * 2);
            }
#pragma unroll
            for (int pr = 0; pr < 4; pr++) {
                int n0 = wn * 64 + pr * 16;
                uint32_t bq[4];
                ldsm_x4t(bq, Bsb + (uint32_t)((k16 + l15) * SBH + n0 + lh * 8) * 2);
                bf[2 * pr][0] = bq[0]; bf[2 * pr][1] = bq[1];
                bf[2 * pr + 1][0] = bq[2]; bf[2 * pr + 1][1] = bq[3];
            }
#pragma unroll
            for (int im = 0; im < 2; im++)
#pragma unroll
                for (int in = 0; in < 8; in++)
                    mma16(acc[im][in], af[im], bf[in][0], bf[in][1]);
        }
    }
#undef LD_STAGE

    if (HALF_OUT) {
        __half* C = (__half*)Cv + zo * sC1 + zi * sC2;
#pragma unroll
        for (int im = 0; im < 2; im++) {
            int m0 = bm * 128 + wm * 32 + im * 16 + g;
#pragma unroll
            for (int in = 0; in < 8; in++) {
                int n0 = bn * 128 + wn * 64 + in * 8 + t4 * 2;
                __half2 h0 = __floats2half2_rn(acc[im][in][0], acc[im][in][1]);
                __half2 h1 = __floats2half2_rn(acc[im][in][2], acc[im][in][3]);
                *(__half2*)(C + (long long)m0 * N + n0)       = h0;
                *(__half2*)(C + (long long)(m0 + 8) * N + n0) = h1;
            }
        }
    } else {
        float* C = (float*)Cv + zo * sC1 + zi * sC2;
#pragma unroll
        for (int im = 0; im < 2; im++) {
            int m0 = bm * 128 + wm * 32 + im * 16 + g;
            float bv0 = bias ? bias[m0]     : 0.f;
            float bv1 = bias ? bias[m0 + 8] : 0.f;
#pragma unroll
            for (int in = 0; in < 8; in++) {
                int n0 = bn * 128 + wn * 64 + in * 8 + t4 * 2;
                *(float2*)(C + (long long)m0 * N + n0) =
                    make_float2(acc[im][in][0] + bv0, acc[im][in][1] + bv0);
                *(float2*)(C + (long long)(m0 + 8) * N + n0) =
                    make_float2(acc[im][in][2] + bv1, acc[im][in][3] + bv1);
            }
        }
    }
}

// ---------------------------------------------------------------------------
// GEMM2 (NT, split-K): ctx_part[slice][bh][e][d] = sum_{n slice} v[e,n]k[d,n]
// ---------------------------------------------------------------------------
__global__ __launch_bounds__(256, 2) void gemm_nt_ctx()
{
    extern __shared__ __half sm[];
    const uint32_t smb  = (uint32_t)__cvta_generic_to_shared(sm);
    const uint32_t mb   = smb;
    const uint32_t asm0 = smb + 32;
    const uint32_t bsm0 = asm0 + 3 * ASTGH * 2;

    const int slice = blockIdx.x;
    const int bh    = blockIdx.y;
    const int b = bh >> 2, h4 = bh & 3;

    const __half* Ag = g_qkvh + ((long long)b * QKVR + 1024 + h4 * 128) * NPIX;
    const __half* Bg = g_qkvh + ((long long)b * QKVR +  512 + h4 * 128) * NPIX;
    float* C = &g_ctx_part[slice][bh][0][0];

    const int tid  = threadIdx.x;
    const int lane = tid & 31, warp = tid >> 5;
    const int g    = lane >> 2, t4 = lane & 3;
    const int wm   = warp & 3,  wn = warp >> 2;
    const int l15  = lane & 15, lh = lane >> 4;

    if (tid == 0) {
        mbar_init(mb, 1); mbar_init(mb + 8, 1); mbar_init(mb + 16, 1);
    }
    __syncthreads();

#define LD_STAGE(st, kk) do {                                                     \
    uint32_t _m = mb + (uint32_t)(st) * 8;                                        \
    if (tid == 0) mbar_expect(_m, STG_BYTES);                                     \
    if (tid < 128) {                                                              \
        bulk_g2s(asm0 + (uint32_t)(st) * (ASTGH * 2) + (uint32_t)tid * (SAH * 2), \
                 Ag + (long long)tid * NPIX + (kk), 64, _m);                      \
    } else {                                                                      \
        int r = tid - 128;                                                        \
        bulk_g2s(bsm0 + (uint32_t)(st) * (ASTGH * 2) + (uint32_t)r * (SAH * 2),   \
                 Bg + (long long)r * NPIX + (kk), 64, _m);                        \
    }                                                                             \
} while (0)

    float acc[2][8][4] = {};
    const int kbeg  = slice * (NPIX / KSPLIT);
    const int niter = (NPIX / KSPLIT) >> 5;   // 16

    LD_STAGE(0, kbeg);
    LD_STAGE(1, kbeg + 32);

    for (int it = 0; it < niter; ++it) {
        mbar_wait(mb + (uint32_t)(it % 3) * 8, (uint32_t)((it / 3) & 1));
        __syncthreads();
        const int ls = it + 2;
        if (ls < niter) LD_STAGE(ls % 3, kbeg + ls * 32);

        const uint32_t Asb = asm0 + (uint32_t)(it % 3) * (ASTGH * 2);
        const uint32_t Bsb = bsm0 + (uint32_t)(it % 3) * (ASTGH * 2);

#pragma unroll
        for (int k16 = 0; k16 < 32; k16 += 16) {
            uint32_t af[2][4], bf[8][2];
#pragma unroll
            for (int im = 0; im < 2; im++) {
                int m = wm * 32 + im * 16 + l15;
                ldsm_x4(af[im], Asb + (uint32_t)(m * SAH + k16 + lh * 8) * 2);
            }
#pragma unroll
            for (int pr = 0; pr < 4; pr++) {
                int d0 = wn * 64 + pr * 16;
                uint32_t bq[4];
                ldsm_x4(bq, Bsb + (uint32_t)((d0 + l15) * SAH + k16 + lh * 8) * 2);
                bf[2 * pr][0] = bq[0]; bf[2 * pr][1] = bq[2];
                bf[2 * pr + 1][0] = bq[1]; bf[2 * pr + 1][1] = bq[3];
            }
#pragma unroll
            for (int im = 0; im < 2; im++)
#pragma unroll
                for (int in = 0; in < 8; in++)
                    mma16(acc[im][in], af[im], bf[in][0], bf[in][1]);
        }
    }
#undef LD_STAGE

#pragma unroll
    for (int im = 0; im < 2; im++) {
        int m0 = wm * 32 + im * 16 + g;
#pragma unroll
        for (int in = 0; in < 8; in++) {
            int n0 = wn * 64 + in * 8 + t4 * 2;
            *(float2*)(C + m0 * 128 + n0)       = make_float2(acc[im][in][0], acc[im][in][1]);
            *(float2*)(C + (m0 + 8) * 128 + n0) = make_float2(acc[im][in][2], acc[im][in][3]);
        }
    }
}

__global__ __launch_bounds__(256) void reduce_ctx()
{
    const long long i = (long long)blockIdx.x * 256 + threadIdx.x;
    const long long total = (long long)BDIM * HEADS * DIMH * DIMH;
    if (i >= total) return;
    const float* p = &g_ctx_part[0][0][0][0];
    float s = 0.f;
#pragma unroll
    for (int k = 0; k < KSPLIT; k++) s += p[(long long)k * total + i];
    (&g_ctxTh[0][0][0])[i] = __float2half_rn(s);
}

// ---------------------------------------------------------------------------
// Softmax over n (4096) on fp16 k rows; register-resident, fp32 math.
// ---------------------------------------------------------------------------
__global__ __launch_bounds__(256) void softmax_k()
{
    const int r = blockIdx.x;
    const int b = r >> 9;
    const int o = 512 + (r & 511);
    __half* row = g_qkvh + ((long long)b * QKVR + o) * NPIX;

    __shared__ float red[8];
    const int tid = threadIdx.x;

    uint4 u0 = ((const uint4*)row)[tid];
    uint4 u1 = ((const uint4*)row)[256 + tid];

    float v[16];
    {
        const __half2* h0 = (const __half2*)&u0;
        const __half2* h1 = (const __half2*)&u1;
#pragma unroll
        for (int i = 0; i < 4; i++) {
            float2 f0 = __half22float2(h0[i]);
            float2 f1 = __half22float2(h1[i]);
            v[2 * i] = f0.x; v[2 * i + 1] = f0.y;
            v[8 + 2 * i] = f1.x; v[8 + 2 * i + 1] = f1.y;
        }
    }

    float mx = v[0];
#pragma unroll
    for (int i = 1; i < 16; i++) mx = fmaxf(mx, v[i]);
#pragma unroll
    for (int off = 16; off; off >>= 1) mx = fmaxf(mx, __shfl_xor_sync(0xffffffffu, mx, off));
    if ((tid & 31) == 0) red[tid >> 5] = mx;
    __syncthreads();
    float m = red[0];
#pragma unroll
    for (int i = 1; i < 8; i++) m = fmaxf(m, red[i]);
    __syncthreads();

    float s = 0.f;
#pragma unroll
    for (int i = 0; i < 16; i++) { v[i] = __expf(v[i] - m); s += v[i]; }
#pragma unroll
    for (int off = 16; off; off >>= 1) s += __shfl_xor_sync(0xffffffffu, s, off);
    if ((tid & 31) == 0) red[tid >> 5] = s;
    __syncthreads();
    float tot = 0.f;
#pragma unroll
    for (int i = 0; i < 8; i++) tot += red[i];
    const float inv = 1.f / tot;

    uint4 w0, w1;
    __half2* o0 = (__half2*)&w0;
    __half2* o1 = (__half2*)&w1;
#pragma unroll
    for (int i = 0; i < 4; i++) {
        o0[i] = __floats2half2_rn(v[2 * i] * inv, v[2 * i + 1] * inv);
        o1[i] = __floats2half2_rn(v[8 + 2 * i] * inv, v[8 + 2 * i + 1] * inv);
    }
    ((uint4*)row)[tid] = w0;
    ((uint4*)row)[256 + tid] = w1;
}

// ---------------------------------------------------------------------------
extern "C" void kernel_launch(void* const* d_in, const int* in_sizes, int n_in,
                              void* d_out, int out_size)
{
    (void)in_sizes; (void)n_in; (void)out_size;
    const float* x     = (const float*)d_in[0];
    const float* w_qkv = (const float*)d_in[1];
    const float* w_out = (const float*)d_in[2];
    const float* b_out = (const float*)d_in[3];
    float* out = (float*)d_out;

    __half *qkv_p, *attn_p, *ctxT_p, *xh_p, *wq_p, *wo_p;
    cudaGetSymbolAddress((void**)&qkv_p,  g_qkvh);
    cudaGetSymbolAddress((void**)&attn_p, g_attnh);
    cudaGetSymbolAddress((void**)&ctxT_p, g_ctxTh);
    cudaGetSymbolAddress((void**)&xh_p,   g_xh);
    cudaGetSymbolAddress((void**)&wq_p,   g_wqh);
    cudaGetSymbolAddress((void**)&wo_p,   g_woh);

    cudaFuncSetAttribute((const void*)gemm_nn<true>,
                         cudaFuncAttributeMaxDynamicSharedMemorySize, SMEM_NN);
    cudaFuncSetAttribute((const void*)gemm_nn<false>,
                         cudaFuncAttributeMaxDynamicSharedMemorySize, SMEM_NN);
    cudaFuncSetAttribute((const void*)gemm_nt_ctx,
                         cudaFuncAttributeMaxDynamicSharedMemorySize, SMEM_NT);

    dim3 blk(256);

    // conversions: x standalone (fusion disproven in R9/R10), weights merged
    f2h<<<(BDIM * CIN * NPIX / 4 + 255) / 256, blk>>>(x, xh_p, BDIM * CIN * NPIX / 4);
    const int na4 = QKVR * CIN / 4, nb4 = CIN * HID / 4;
    f2h2<<<(na4 + nb4 + 255) / 256, blk>>>(w_qkv, wq_p, na4, w_out, wo_p, nb4);

    // GEMM1: qkv[b] = w_qkv @ x[b]  -> fp16
    gemm_nn<true><<<dim3(NPIX / 128, QKVR / 128, BDIM), blk, SMEM_NN>>>(
        wq_p, 0, 0, CIN,
        xh_p, (long long)CIN * NPIX, 0,
        qkv_p, (long long)QKVR * NPIX, 0,
        nullptr, 1, NPIX, CIN);

    softmax_k<<<BDIM * HEADS * DIMH, blk>>>();

    gemm_nt_ctx<<<dim3(KSPLIT, BDIM * HEADS), blk, SMEM_NT>>>();
    reduce_ctx<<<(BDIM * HEADS * DIMH * DIMH) / 256, blk>>>();

    // GEMM3: attn[b,h] = ctxT[b,h] @ q[b,h]  -> fp16
    gemm_nn<true><<<dim3(NPIX / 128, 1, BDIM * HEADS), blk, SMEM_NN>>>(
        ctxT_p, (long long)HEADS * DIMH * DIMH, (long long)DIMH * DIMH, DIMH,
        qkv_p, (long long)QKVR * NPIX, (long long)DIMH * NPIX,
        attn_p, (long long)HID * NPIX, (long long)DIMH * NPIX,
        nullptr, HEADS, NPIX, DIMH);

    // GEMM4: out[b] = w_out @ attn[b] + b_out  -> fp32
    gemm_nn<false><<<dim3(NPIX / 128, CIN / 128, BDIM), blk, SMEM_NN>>>(
        wo_p, 0, 0, HID,
        attn_p, (long long)HID * NPIX, 0,
        out, (long long)CIN * NPIX, 0,
        b_out, 1, NPIX, HID);
}

// round 12
// speedup vs baseline: 1.2665x; 1.2665x over previous
#include <cuda_runtime.h>
#include <cuda_fp16.h>
#include <cstdint>

// ---------------------------------------------------------------------------
// LinearAttention, fp16 mma.sync m16n8k16 (fp32 accum) + ldmatrix + cp.async.
// R12: GEMM1/GEMM4 use a 256x128 tile (512 threads) to cut the LDGSTS-per-HMMA
// ratio from 2.0 to 1.5 (R6 profile: LSU issue rate binds at tensor=42%).
// GEMM2/GEMM3/softmax/reduce identical to the R6 207.7us baseline.
// ---------------------------------------------------------------------------

#define BDIM   8
#define CIN    256
#define NPIX   4096
#define HEADS  4
#define DIMH   128
#define HID    512
#define QKVR   1536
#define KSPLIT 8

#define SAH    40                 // A smem stride (halfs): 80B
#define SBH    136                // B smem stride (halfs): 272B
#define ASTGH  (128 * SAH)        // 5120 halfs (128-row tiles)
#define A2STGH (256 * SAH)        // 10240 halfs (256-row tiles)
#define BSTGH  (32 * SBH)         // 4352 halfs
#define SMEM_NN  (3 * (ASTGH + BSTGH) * 2)    // 56832
#define SMEM_256 (3 * (A2STGH + BSTGH) * 2)   // 87552
#define SMEM_NT  (3 * 2 * ASTGH * 2)          // 61440

__device__ __half g_qkvh[(size_t)BDIM * QKVR * NPIX];
__device__ __half g_attnh[(size_t)BDIM * HID * NPIX];
__device__ float  g_ctx_part[KSPLIT][BDIM * HEADS][DIMH][DIMH];
__device__ __half g_ctxTh[BDIM * HEADS][DIMH][DIMH];
__device__ __half g_xh [(size_t)BDIM * CIN * NPIX];
__device__ __half g_wqh[QKVR * CIN];
__device__ __half g_woh[CIN * HID];

// ---------------- helpers ----------------
__device__ __forceinline__ void cpa16(uint32_t d, const void* s) {
    asm volatile("cp.async.cg.shared.global [%0], [%1], 16;\n" :: "r"(d), "l"(s));
}
__device__ __forceinline__ void cp_commit() { asm volatile("cp.async.commit_group;\n"); }
template<int N> __device__ __forceinline__ void cp_wait() {
    asm volatile("cp.async.wait_group %0;\n" :: "n"(N));
}
__device__ __forceinline__ void ldsm_x4(uint32_t r[4], uint32_t a) {
    asm volatile("ldmatrix.sync.aligned.m8n8.x4.shared.b16 {%0,%1,%2,%3}, [%4];"
        : "=r"(r[0]), "=r"(r[1]), "=r"(r[2]), "=r"(r[3]) : "r"(a));
}
__device__ __forceinline__ void ldsm_x4t(uint32_t r[4], uint32_t a) {
    asm volatile("ldmatrix.sync.aligned.m8n8.x4.trans.shared.b16 {%0,%1,%2,%3}, [%4];"
        : "=r"(r[0]), "=r"(r[1]), "=r"(r[2]), "=r"(r[3]) : "r"(a));
}
__device__ __forceinline__ void mma16(float c[4], const uint32_t a[4], const uint32_t b0, const uint32_t b1) {
    asm volatile(
        "mma.sync.aligned.m16n8k16.row.col.f32.f16.f16.f32 "
        "{%0,%1,%2,%3}, {%4,%5,%6,%7}, {%8,%9}, {%0,%1,%2,%3};"
        : "+f"(c[0]), "+f"(c[1]), "+f"(c[2]), "+f"(c[3])
        : "r"(a[0]), "r"(a[1]), "r"(a[2]), "r"(a[3]), "r"(b0), "r"(b1));
}

// ---------------------------------------------------------------------------
__global__ __launch_bounds__(256) void f2h(
    const float* __restrict__ in, __half* __restrict__ out, int n4)
{
    int i = blockIdx.x * 256 + threadIdx.x;
    if (i < n4) {
        float4 v = ((const float4*)in)[i];
        __half2 h0 = __floats2half2_rn(v.x, v.y);
        __half2 h1 = __floats2half2_rn(v.z, v.w);
        uint2 u;
        u.x = *(uint32_t*)&h0;
        u.y = *(uint32_t*)&h1;
        ((uint2*)out)[i] = u;
    }
}
__global__ __launch_bounds__(256) void f2h2(
    const float* __restrict__ a, __half* __restrict__ oa, int na4,
    const float* __restrict__ b, __half* __restrict__ ob, int nb4)
{
    int i = blockIdx.x * 256 + threadIdx.x;
    const float* src; __half* dst; int j;
    if (i < na4) { src = a; dst = oa; j = i; }
    else         { j = i - na4; if (j >= nb4) return; src = b; dst = ob; }
    float4 v = ((const float4*)src)[j];
    __half2 h0 = __floats2half2_rn(v.x, v.y);
    __half2 h1 = __floats2half2_rn(v.z, v.w);
    uint2 u;
    u.x = *(uint32_t*)&h0;
    u.y = *(uint32_t*)&h1;
    ((uint2*)dst)[j] = u;
}

// ---------------------------------------------------------------------------
// 256x128-tile NN GEMM fp16 (512 threads, warp grid 4m x 4n). BK=32, 3-stage.
// ---------------------------------------------------------------------------
template<bool HALF_OUT>
__global__ __launch_bounds__(512, 1) void gemm_nn_256(
    const __half* __restrict__ A, long long sA1, long long sA2, int lda,
    const __half* __restrict__ B, long long sB1, long long sB2,
    void*         __restrict__ Cv, long long sC1, long long sC2,
    const float* __restrict__ bias,
    int zdiv, int N, int K)
{
    extern __shared__ __half sm[];
    __half* Asm = sm;                  // [3][256][SAH]
    __half* Bsm = sm + 3 * A2STGH;     // [3][32][SBH]

    const int bm = blockIdx.y, bn = blockIdx.x;
    const int zo = blockIdx.z / zdiv, zi = blockIdx.z % zdiv;
    A += zo * sA1 + zi * sA2;
    B += zo * sB1 + zi * sB2;

    const int tid  = threadIdx.x;
    const int lane = tid & 31, warp = tid >> 5;   // 0..15
    const int g    = lane >> 2, t4 = lane & 3;
    const int wm   = warp & 3,  wn = warp >> 2;   // 4x4 warp grid
    const int l15  = lane & 15, lh = lane >> 4;

    const __half* Ag = A + (long long)bm * 256 * lda;
    const __half* Bg = B + bn * 128;

    const uint32_t asm0 = (uint32_t)__cvta_generic_to_shared(Asm);
    const uint32_t bsm0 = (uint32_t)__cvta_generic_to_shared(Bsm);

#define LD256(st, kk) do {                                                       \
    uint32_t ab = asm0 + (uint32_t)(st) * (A2STGH * 2);                          \
    uint32_t bb = bsm0 + (uint32_t)(st) * (BSTGH * 2);                           \
    _Pragma("unroll")                                                            \
    for (int t = 0; t < 2; t++) {                                                \
        int idx = t * 512 + tid;                                                 \
        int row = idx >> 2, ch = idx & 3;                                        \
        cpa16(ab + (uint32_t)(row * SAH + ch * 8) * 2,                           \
              Ag + (long long)row * lda + (kk) + ch * 8);                        \
    }                                                                            \
    {                                                                            \
        int kr = tid >> 4, nc = tid & 15;                                        \
        cpa16(bb + (uint32_t)(kr * SBH + nc * 8) * 2,                            \
              Bg + (long long)((kk) + kr) * N + nc * 8);                         \
    }                                                                            \
    cp_commit();                                                                 \
} while (0)

    float acc[4][4][4] = {};
    const int niter = K >> 5;

    LD256(0, 0);
    LD256(1, 32);

    for (int it = 0; it < niter; ++it) {
        cp_wait<1>();
        __syncthreads();
        const int ls = it + 2;
        if (ls < niter) { LD256(ls % 3, ls * 32); }
        else            { cp_commit(); }

        const uint32_t Asb = asm0 + (uint32_t)(it % 3) * (A2STGH * 2);
        const uint32_t Bsb = bsm0 + (uint32_t)(it % 3) * (BSTGH * 2);

#pragma unroll
        for (int k16 = 0; k16 < 32; k16 += 16) {
            uint32_t af[4][4], bf[4][2];
#pragma unroll
            for (int im = 0; im < 4; im++) {
                int m = wm * 64 + im * 16 + l15;
                ldsm_x4(af[im], Asb + (uint32_t)(m * SAH + k16 + lh * 8) * 2);
            }
#pragma unroll
            for (int pr = 0; pr < 2; pr++) {
                int n0 = wn * 32 + pr * 16;
                uint32_t bq[4];
                ldsm_x4t(bq, Bsb + (uint32_t)((k16 + l15) * SBH + n0 + lh * 8) * 2);
                bf[2 * pr][0] = bq[0]; bf[2 * pr][1] = bq[1];
                bf[2 * pr + 1][0] = bq[2]; bf[2 * pr + 1][1] = bq[3];
            }
#pragma unroll
            for (int im = 0; im < 4; im++)
#pragma unroll
                for (int in = 0; in < 4; in++)
                    mma16(acc[im][in], af[im], bf[in][0], bf[in][1]);
        }
    }
#undef LD256

    if (HALF_OUT) {
        __half* C = (__half*)Cv + zo * sC1 + zi * sC2;
#pragma unroll
        for (int im = 0; im < 4; im++) {
            int m0 = bm * 256 + wm * 64 + im * 16 + g;
#pragma unroll
            for (int in = 0; in < 4; in++) {
                int n0 = bn * 128 + wn * 32 + in * 8 + t4 * 2;
                __half2 h0 = __floats2half2_rn(acc[im][in][0], acc[im][in][1]);
                __half2 h1 = __floats2half2_rn(acc[im][in][2], acc[im][in][3]);
                *(__half2*)(C + (long long)m0 * N + n0)       = h0;
                *(__half2*)(C + (long long)(m0 + 8) * N + n0) = h1;
            }
        }
    } else {
        float* C = (float*)Cv + zo * sC1 + zi * sC2;
#pragma unroll
        for (int im = 0; im < 4; im++) {
            int m0 = bm * 256 + wm * 64 + im * 16 + g;
            float bv0 = bias ? bias[m0]     : 0.f;
            float bv1 = bias ? bias[m0 + 8] : 0.f;
#pragma unroll
            for (int in = 0; in < 4; in++) {
                int n0 = bn * 128 + wn * 32 + in * 8 + t4 * 2;
                *(float2*)(C + (long long)m0 * N + n0) =
                    make_float2(acc[im][in][0] + bv0, acc[im][in][1] + bv0);
                *(float2*)(C + (long long)(m0 + 8) * N + n0) =
                    make_float2(acc[im][in][2] + bv1, acc[im][in][3] + bv1);
            }
        }
    }
}

// ---------------------------------------------------------------------------
// 128x128-tile NN GEMM fp16 (R6 exact) — used for GEMM3 (M=128).
// ---------------------------------------------------------------------------
template<bool HALF_OUT>
__global__ __launch_bounds__(256, 2) void gemm_nn(
    const __half* __restrict__ A, long long sA1, long long sA2, int lda,
    const __half* __restrict__ B, long long sB1, long long sB2,
    void*         __restrict__ Cv, long long sC1, long long sC2,
    const float* __restrict__ bias,
    int zdiv, int N, int K)
{
    extern __shared__ __half sm[];
    __half* Asm = sm;                 // [3][128][SAH]
    __half* Bsm = sm + 3 * ASTGH;     // [3][32][SBH]

    const int bm = blockIdx.y, bn = blockIdx.x;
    const int zo = blockIdx.z / zdiv, zi = blockIdx.z % zdiv;
    A += zo * sA1 + zi * sA2;
    B += zo * sB1 + zi * sB2;

    const int tid  = threadIdx.x;
    const int lane = tid & 31, warp = tid >> 5;
    const int g    = lane >> 2, t4 = lane & 3;
    const int wm   = warp & 3,  wn = warp >> 2;
    const int l15  = lane & 15, lh = lane >> 4;

    const __half* Ag = A + (long long)bm * 128 * lda;
    const __half* Bg = B + bn * 128;

    const uint32_t asm0 = (uint32_t)__cvta_generic_to_shared(Asm);
    const uint32_t bsm0 = (uint32_t)__cvta_generic_to_shared(Bsm);

#define LD_NN(st, kk) do {                                                       \
    uint32_t ab = asm0 + (uint32_t)(st) * (ASTGH * 2);                           \
    uint32_t bb = bsm0 + (uint32_t)(st) * (BSTGH * 2);                           \
    _Pragma("unroll")                                                            \
    for (int t = 0; t < 2; t++) {                                                \
        int idx = t * 256 + tid;                                                 \
        int row = idx >> 2, ch = idx & 3;                                        \
        cpa16(ab + (uint32_t)(row * SAH + ch * 8) * 2,                           \
              Ag + (long long)row * lda + (kk) + ch * 8);                        \
        int kr = idx >> 4, nc = idx & 15;                                        \
        cpa16(bb + (uint32_t)(kr * SBH + nc * 8) * 2,                            \
              Bg + (long long)((kk) + kr) * N + nc * 8);                         \
    }                                                                            \
    cp_commit();                                                                 \
} while (0)

    float acc[2][8][4] = {};
    const int niter = K >> 5;

    LD_NN(0, 0);
    LD_NN(1, 32);

    for (int it = 0; it < niter; ++it) {
        cp_wait<1>();
        __syncthreads();
        const int ls = it + 2;
        if (ls < niter) { LD_NN(ls % 3, ls * 32); }
        else            { cp_commit(); }

        const uint32_t Asb = asm0 + (uint32_t)(it % 3) * (ASTGH * 2);
        const uint32_t Bsb = bsm0 + (uint32_t)(it % 3) * (BSTGH * 2);

#pragma unroll
        for (int k16 = 0; k16 < 32; k16 += 16) {
            uint32_t af[2][4], bf[8][2];
#pragma unroll
            for (int im = 0; im < 2; im++) {
                int m = wm * 32 + im * 16 + l15;
                ldsm_x4(af[im], Asb + (uint32_t)(m * SAH + k16 + lh * 8) * 2);
            }
#pragma unroll
            for (int pr = 0; pr < 4; pr++) {
                int n0 = wn * 64 + pr * 16;
                uint32_t bq[4];
                ldsm_x4t(bq, Bsb + (uint32_t)((k16 + l15) * SBH + n0 + lh * 8) * 2);
                bf[2 * pr][0] = bq[0]; bf[2 * pr][1] = bq[1];
                bf[2 * pr + 1][0] = bq[2]; bf[2 * pr + 1][1] = bq[3];
            }
#pragma unroll
            for (int im = 0; im < 2; im++)
#pragma unroll
                for (int in = 0; in < 8; in++)
                    mma16(acc[im][in], af[im], bf[in][0], bf[in][1]);
        }
    }
#undef LD_NN

    if (HALF_OUT) {
        __half* C = (__half*)Cv + zo * sC1 + zi * sC2;
#pragma unroll
        for (int im = 0; im < 2; im++) {
            int m0 = bm * 128 + wm * 32 + im * 16 + g;
#pragma unroll
            for (int in = 0; in < 8; in++) {
                int n0 = bn * 128 + wn * 64 + in * 8 + t4 * 2;
                __half2 h0 = __floats2half2_rn(acc[im][in][0], acc[im][in][1]);
                __half2 h1 = __floats2half2_rn(acc[im][in][2], acc[im][in][3]);
                *(__half2*)(C + (long long)m0 * N + n0)       = h0;
                *(__half2*)(C + (long long)(m0 + 8) * N + n0) = h1;
            }
        }
    } else {
        float* C = (float*)Cv + zo * sC1 + zi * sC2;
#pragma unroll
        for (int im = 0; im < 2; im++) {
            int m0 = bm * 128 + wm * 32 + im * 16 + g;
            float bv0 = bias ? bias[m0]     : 0.f;
            float bv1 = bias ? bias[m0 + 8] : 0.f;
#pragma unroll
            for (int in = 0; in < 8; in++) {
                int n0 = bn * 128 + wn * 64 + in * 8 + t4 * 2;
                *(float2*)(C + (long long)m0 * N + n0) =
                    make_float2(acc[im][in][0] + bv0, acc[im][in][1] + bv0);
                *(float2*)(C + (long long)(m0 + 8) * N + n0) =
                    make_float2(acc[im][in][2] + bv1, acc[im][in][3] + bv1);
            }
        }
    }
}

// ---------------------------------------------------------------------------
// GEMM2 (NT, split-K): ctx_part[slice][bh][e][d] = sum_{n slice} v[e,n]k[d,n]
// ---------------------------------------------------------------------------
__global__ __launch_bounds__(256, 2) void gemm_nt_ctx()
{
    extern __shared__ __half sm[];
    __half* Asm = sm;                 // [3][128][SAH] (v: [e][k])
    __half* Bsm = sm + 3 * ASTGH;     // [3][128][SAH] (k: [d][k])

    const int slice = blockIdx.x;
    const int bh    = blockIdx.y;
    const int b = bh >> 2, h4 = bh & 3;

    const __half* Ag = g_qkvh + ((long long)b * QKVR + 1024 + h4 * 128) * NPIX;
    const __half* Bg = g_qkvh + ((long long)b * QKVR +  512 + h4 * 128) * NPIX;
    float* C = &g_ctx_part[slice][bh][0][0];

    const int tid  = threadIdx.x;
    const int lane = tid & 31, warp = tid >> 5;
    const int g    = lane >> 2, t4 = lane & 3;
    const int wm   = warp & 3,  wn = warp >> 2;
    const int l15  = lane & 15, lh = lane >> 4;

    const uint32_t asm0 = (uint32_t)__cvta_generic_to_shared(Asm);
    const uint32_t bsm0 = (uint32_t)__cvta_generic_to_shared(Bsm);

#define LD_NT(st, kk) do {                                                       \
    uint32_t ab = asm0 + (uint32_t)(st) * (ASTGH * 2);                           \
    uint32_t bb = bsm0 + (uint32_t)(st) * (ASTGH * 2);                           \
    _Pragma("unroll")                                                            \
    for (int t = 0; t < 2; t++) {                                                \
        int idx = t * 256 + tid;                                                 \
        int row = idx >> 2, ch = idx & 3;                                        \
        uint32_t so = (uint32_t)(row * SAH + ch * 8) * 2;                        \
        cpa16(ab + so, Ag + (long long)row * NPIX + (kk) + ch * 8);              \
        cpa16(bb + so, Bg + (long long)row * NPIX + (kk) + ch * 8);              \
    }                                                                            \
    cp_commit();                                                                 \
} while (0)

    float acc[2][8][4] = {};
    const int kbeg  = slice * (NPIX / KSPLIT);
    const int niter = (NPIX / KSPLIT) >> 5;   // 16

    LD_NT(0, kbeg);
    LD_NT(1, kbeg + 32);

    for (int it = 0; it < niter; ++it) {
        cp_wait<1>();
        __syncthreads();
        const int ls = it + 2;
        if (ls < niter) { LD_NT(ls % 3, kbeg + ls * 32); }
        else            { cp_commit(); }

        const uint32_t Asb = asm0 + (uint32_t)(it % 3) * (ASTGH * 2);
        const uint32_t Bsb = bsm0 + (uint32_t)(it % 3) * (ASTGH * 2);

#pragma unroll
        for (int k16 = 0; k16 < 32; k16 += 16) {
            uint32_t af[2][4], bf[8][2];
#pragma unroll
            for (int im = 0; im < 2; im++) {
                int m = wm * 32 + im * 16 + l15;
                ldsm_x4(af[im], Asb + (uint32_t)(m * SAH + k16 + lh * 8) * 2);
            }
#pragma unroll
            for (int pr = 0; pr < 4; pr++) {
                int d0 = wn * 64 + pr * 16;
                uint32_t bq[4];
                ldsm_x4(bq, Bsb + (uint32_t)((d0 + l15) * SAH + k16 + lh * 8) * 2);
                bf[2 * pr][0] = bq[0]; bf[2 * pr][1] = bq[2];
                bf[2 * pr + 1][0] = bq[1]; bf[2 * pr + 1][1] = bq[3];
            }
#pragma unroll
            for (int im = 0; im < 2; im++)
#pragma unroll
                for (int in = 0; in < 8; in++)
                    mma16(acc[im][in], af[im], bf[in][0], bf[in][1]);
        }
    }
#undef LD_NT

#pragma unroll
    for (int im = 0; im < 2; im++) {
        int m0 = wm * 32 + im * 16 + g;
#pragma unroll
        for (int in = 0; in < 8; in++) {
            int n0 = wn * 64 + in * 8 + t4 * 2;
            *(float2*)(C + m0 * 128 + n0)       = make_float2(acc[im][in][0], acc[im][in][1]);
            *(float2*)(C + (m0 + 8) * 128 + n0) = make_float2(acc[im][in][2], acc[im][in][3]);
        }
    }
}

__global__ __launch_bounds__(256) void reduce_ctx()
{
    const long long i = (long long)blockIdx.x * 256 + threadIdx.x;
    const long long total = (long long)BDIM * HEADS * DIMH * DIMH;
    if (i >= total) return;
    const float* p = &g_ctx_part[0][0][0][0];
    float s = 0.f;
#pragma unroll
    for (int k = 0; k < KSPLIT; k++) s += p[(long long)k * total + i];
    (&g_ctxTh[0][0][0])[i] = __float2half_rn(s);
}

// ---------------------------------------------------------------------------
// Softmax over n (4096) on fp16 k rows; register-resident, fp32 math.
// ---------------------------------------------------------------------------
__global__ __launch_bounds__(256) void softmax_k()
{
    const int r = blockIdx.x;
    const int b = r >> 9;
    const int o = 512 + (r & 511);
    __half* row = g_qkvh + ((long long)b * QKVR + o) * NPIX;

    __shared__ float red[8];
    const int tid = threadIdx.x;

    uint4 u0 = ((const uint4*)row)[tid];
    uint4 u1 = ((const uint4*)row)[256 + tid];

    float v[16];
    {
        const __half2* h0 = (const __half2*)&u0;
        const __half2* h1 = (const __half2*)&u1;
#pragma unroll
        for (int i = 0; i < 4; i++) {
            float2 f0 = __half22float2(h0[i]);
            float2 f1 = __half22float2(h1[i]);
            v[2 * i] = f0.x; v[2 * i + 1] = f0.y;
            v[8 + 2 * i] = f1.x; v[8 + 2 * i + 1] = f1.y;
        }
    }

    float mx = v[0];
#pragma unroll
    for (int i = 1; i < 16; i++) mx = fmaxf(mx, v[i]);
#pragma unroll
    for (int off = 16; off; off >>= 1) mx = fmaxf(mx, __shfl_xor_sync(0xffffffffu, mx, off));
    if ((tid & 31) == 0) red[tid >> 5] = mx;
    __syncthreads();
    float m = red[0];
#pragma unroll
    for (int i = 1; i < 8; i++) m = fmaxf(m, red[i]);
    __syncthreads();

    float s = 0.f;
#pragma unroll
    for (int i = 0; i < 16; i++) { v[i] = __expf(v[i] - m); s += v[i]; }
#pragma unroll
    for (int off = 16; off; off >>= 1) s += __shfl_xor_sync(0xffffffffu, s, off);
    if ((tid & 31) == 0) red[tid >> 5] = s;
    __syncthreads();
    float tot = 0.f;
#pragma unroll
    for (int i = 0; i < 8; i++) tot += red[i];
    const float inv = 1.f / tot;

    uint4 w0, w1;
    __half2* o0 = (__half2*)&w0;
    __half2* o1 = (__half2*)&w1;
#pragma unroll
    for (int i = 0; i < 4; i++) {
        o0[i] = __floats2half2_rn(v[2 * i] * inv, v[2 * i + 1] * inv);
        o1[i] = __floats2half2_rn(v[8 + 2 * i] * inv, v[8 + 2 * i + 1] * inv);
    }
    ((uint4*)row)[tid] = w0;
    ((uint4*)row)[256 + tid] = w1;
}

// ---------------------------------------------------------------------------
extern "C" void kernel_launch(void* const* d_in, const int* in_sizes, int n_in,
                              void* d_out, int out_size)
{
    (void)in_sizes; (void)n_in; (void)out_size;
    const float* x     = (const float*)d_in[0];
    const float* w_qkv = (const float*)d_in[1];
    const float* w_out = (const float*)d_in[2];
    const float* b_out = (const float*)d_in[3];
    float* out = (float*)d_out;

    __half *qkv_p, *attn_p, *ctxT_p, *xh_p, *wq_p, *wo_p;
    cudaGetSymbolAddress((void**)&qkv_p,  g_qkvh);
    cudaGetSymbolAddress((void**)&attn_p, g_attnh);
    cudaGetSymbolAddress((void**)&ctxT_p, g_ctxTh);
    cudaGetSymbolAddress((void**)&xh_p,   g_xh);
    cudaGetSymbolAddress((void**)&wq_p,   g_wqh);
    cudaGetSymbolAddress((void**)&wo_p,   g_woh);

    cudaFuncSetAttribute((const void*)gemm_nn_256<true>,
                         cudaFuncAttributeMaxDynamicSharedMemorySize, SMEM_256);
    cudaFuncSetAttribute((const void*)gemm_nn_256<false>,
                         cudaFuncAttributeMaxDynamicSharedMemorySize, SMEM_256);
    cudaFuncSetAttribute((const void*)gemm_nn<true>,
                         cudaFuncAttributeMaxDynamicSharedMemorySize, SMEM_NN);
    cudaFuncSetAttribute((const void*)gemm_nt_ctx,
                         cudaFuncAttributeMaxDynamicSharedMemorySize, SMEM_NT);

    dim3 blk(256);

    // conversions
    f2h<<<(BDIM * CIN * NPIX / 4 + 255) / 256, blk>>>(x, xh_p, BDIM * CIN * NPIX / 4);
    const int na4 = QKVR * CIN / 4, nb4 = CIN * HID / 4;
    f2h2<<<(na4 + nb4 + 255) / 256, blk>>>(w_qkv, wq_p, na4, w_out, wo_p, nb4);

    // GEMM1: qkv[b] = w_qkv @ x[b]  -> fp16   (256-row tiles)
    gemm_nn_256<true><<<dim3(NPIX / 128, QKVR / 256, BDIM), dim3(512), SMEM_256>>>(
        wq_p, 0, 0, CIN,
        xh_p, (long long)CIN * NPIX, 0,
        qkv_p, (long long)QKVR * NPIX, 0,
        nullptr, 1, NPIX, CIN);

    softmax_k<<<BDIM * HEADS * DIMH, blk>>>();

    gemm_nt_ctx<<<dim3(KSPLIT, BDIM * HEADS), blk, SMEM_NT>>>();
    reduce_ctx<<<(BDIM * HEADS * DIMH * DIMH) / 256, blk>>>();

    // GEMM3: attn[b,h] = ctxT[b,h] @ q[b,h]  -> fp16   (128-row tiles, M=128)
    gemm_nn<true><<<dim3(NPIX / 128, 1, BDIM * HEADS), blk, SMEM_NN>>>(
        ctxT_p, (long long)HEADS * DIMH * DIMH, (long long)DIMH * DIMH, DIMH,
        qkv_p, (long long)QKVR * NPIX, (long long)DIMH * NPIX,
        attn_p, (long long)HID * NPIX, (long long)DIMH * NPIX,
        nullptr, HEADS, NPIX, DIMH);

    // GEMM4: out[b] = w_out @ attn[b] + b_out  -> fp32  (M=256: one 256-tile)
    gemm_nn_256<false><<<dim3(NPIX / 128, CIN / 256, BDIM), dim3(512), SMEM_256>>>(
        wo_p, 0, 0, HID,
        attn_p, (long long)HID * NPIX, 0,
        out, (long long)CIN * NPIX, 0,
        b_out, 1, NPIX, HID);
}

// round 13
// speedup vs baseline: 1.3793x; 1.0891x over previous
#include <cuda_runtime.h>
#include <cuda_fp16.h>
#include <cstdint>

// ---------------------------------------------------------------------------
// LinearAttention, fp16 mma.sync m16n8k16 (fp32 accum) + ldmatrix + cp.async.
// R13: R6 baseline (207.7us) + 4-stage pipeline (deeper latency hiding at
// unchanged 2 CTA/SM) + KSPLIT 16 for GEMM2 (occupancy 19%->~38%).
// ---------------------------------------------------------------------------

#define BDIM   8
#define CIN    256
#define NPIX   4096
#define HEADS  4
#define DIMH   128
#define HID    512
#define QKVR   1536
#define KSPLIT 16

#define NSTG   4
#define SAH    40                 // A smem stride (halfs): 80B
#define SBH    136                // B smem stride (halfs): 272B
#define ASTGH  (128 * SAH)        // 5120 halfs
#define BSTGH  (32 * SBH)         // 4352 halfs
#define SMEM_NN (NSTG * (ASTGH + BSTGH) * 2)   // 75776
#define SMEM_NT (NSTG * 2 * ASTGH * 2)         // 81920

__device__ __half g_qkvh[(size_t)BDIM * QKVR * NPIX];
__device__ __half g_attnh[(size_t)BDIM * HID * NPIX];
__device__ float  g_ctx_part[KSPLIT][BDIM * HEADS][DIMH][DIMH];
__device__ __half g_ctxTh[BDIM * HEADS][DIMH][DIMH];
__device__ __half g_xh [(size_t)BDIM * CIN * NPIX];
__device__ __half g_wqh[QKVR * CIN];
__device__ __half g_woh[CIN * HID];

// ---------------- helpers ----------------
__device__ __forceinline__ void cpa16(uint32_t d, const void* s) {
    asm volatile("cp.async.cg.shared.global [%0], [%1], 16;\n" :: "r"(d), "l"(s));
}
__device__ __forceinline__ void cp_commit() { asm volatile("cp.async.commit_group;\n"); }
template<int N> __device__ __forceinline__ void cp_wait() {
    asm volatile("cp.async.wait_group %0;\n" :: "n"(N));
}
__device__ __forceinline__ void ldsm_x4(uint32_t r[4], uint32_t a) {
    asm volatile("ldmatrix.sync.aligned.m8n8.x4.shared.b16 {%0,%1,%2,%3}, [%4];"
        : "=r"(r[0]), "=r"(r[1]), "=r"(r[2]), "=r"(r[3]) : "r"(a));
}
__device__ __forceinline__ void ldsm_x4t(uint32_t r[4], uint32_t a) {
    asm volatile("ldmatrix.sync.aligned.m8n8.x4.trans.shared.b16 {%0,%1,%2,%3}, [%4];"
        : "=r"(r[0]), "=r"(r[1]), "=r"(r[2]), "=r"(r[3]) : "r"(a));
}
__device__ __forceinline__ void mma16(float c[4], const uint32_t a[4], const uint32_t b0, const uint32_t b1) {
    asm volatile(
        "mma.sync.aligned.m16n8k16.row.col.f32.f16.f16.f32 "
        "{%0,%1,%2,%3}, {%4,%5,%6,%7}, {%8,%9}, {%0,%1,%2,%3};"
        : "+f"(c[0]), "+f"(c[1]), "+f"(c[2]), "+f"(c[3])
        : "r"(a[0]), "r"(a[1]), "r"(a[2]), "r"(a[3]), "r"(b0), "r"(b1));
}

// ---------------------------------------------------------------------------
__global__ __launch_bounds__(256) void f2h(
    const float* __restrict__ in, __half* __restrict__ out, int n4)
{
    int i = blockIdx.x * 256 + threadIdx.x;
    if (i < n4) {
        float4 v = ((const float4*)in)[i];
        __half2 h0 = __floats2half2_rn(v.x, v.y);
        __half2 h1 = __floats2half2_rn(v.z, v.w);
        uint2 u;
        u.x = *(uint32_t*)&h0;
        u.y = *(uint32_t*)&h1;
        ((uint2*)out)[i] = u;
    }
}
__global__ __launch_bounds__(256) void f2h2(
    const float* __restrict__ a, __half* __restrict__ oa, int na4,
    const float* __restrict__ b, __half* __restrict__ ob, int nb4)
{
    int i = blockIdx.x * 256 + threadIdx.x;
    const float* src; __half* dst; int j;
    if (i < na4) { src = a; dst = oa; j = i; }
    else         { j = i - na4; if (j >= nb4) return; src = b; dst = ob; }
    float4 v = ((const float4*)src)[j];
    __half2 h0 = __floats2half2_rn(v.x, v.y);
    __half2 h1 = __floats2half2_rn(v.z, v.w);
    uint2 u;
    u.x = *(uint32_t*)&h0;
    u.y = *(uint32_t*)&h1;
    ((uint2*)dst)[j] = u;
}

// ---------------------------------------------------------------------------
// NN GEMM fp16: C = A[M,K]@B[K,N] (+bias). 128x128 tile, BK=32, 4-stage.
// ---------------------------------------------------------------------------
template<bool HALF_OUT>
__global__ __launch_bounds__(256, 2) void gemm_nn(
    const __half* __restrict__ A, long long sA1, long long sA2, int lda,
    const __half* __restrict__ B, long long sB1, long long sB2,
    void*         __restrict__ Cv, long long sC1, long long sC2,
    const float* __restrict__ bias,
    int zdiv, int N, int K)
{
    extern __shared__ __half sm[];
    __half* Asm = sm;                    // [NSTG][128][SAH]
    __half* Bsm = sm + NSTG * ASTGH;     // [NSTG][32][SBH]

    const int bm = blockIdx.y, bn = blockIdx.x;
    const int zo = blockIdx.z / zdiv, zi = blockIdx.z % zdiv;
    A += zo * sA1 + zi * sA2;
    B += zo * sB1 + zi * sB2;

    const int tid  = threadIdx.x;
    const int lane = tid & 31, warp = tid >> 5;
    const int g    = lane >> 2, t4 = lane & 3;
    const int wm   = warp & 3,  wn = warp >> 2;
    const int l15  = lane & 15, lh = lane >> 4;

    const __half* Ag = A + (long long)bm * 128 * lda;
    const __half* Bg = B + bn * 128;

    const uint32_t asm0 = (uint32_t)__cvta_generic_to_shared(Asm);
    const uint32_t bsm0 = (uint32_t)__cvta_generic_to_shared(Bsm);

#define LD_NN(st, kk) do {                                                       \
    uint32_t ab = asm0 + (uint32_t)(st) * (ASTGH * 2);                           \
    uint32_t bb = bsm0 + (uint32_t)(st) * (BSTGH * 2);                           \
    _Pragma("unroll")                                                            \
    for (int t = 0; t < 2; t++) {                                                \
        int idx = t * 256 + tid;                                                 \
        int row = idx >> 2, ch = idx & 3;                                        \
        cpa16(ab + (uint32_t)(row * SAH + ch * 8) * 2,                           \
              Ag + (long long)row * lda + (kk) + ch * 8);                        \
        int kr = idx >> 4, nc = idx & 15;                                        \
        cpa16(bb + (uint32_t)(kr * SBH + nc * 8) * 2,                            \
              Bg + (long long)((kk) + kr) * N + nc * 8);                         \
    }                                                                            \
    cp_commit();                                                                 \
} while (0)

    float acc[2][8][4] = {};
    const int niter = K >> 5;

    LD_NN(0, 0);
    LD_NN(1, 32);
    LD_NN(2, 64);

    for (int it = 0; it < niter; ++it) {
        cp_wait<NSTG - 2>();
        __syncthreads();
        const int ls = it + NSTG - 1;
        if (ls < niter) { LD_NN(ls % NSTG, ls * 32); }
        else            { cp_commit(); }

        const uint32_t Asb = asm0 + (uint32_t)(it % NSTG) * (ASTGH * 2);
        const uint32_t Bsb = bsm0 + (uint32_t)(it % NSTG) * (BSTGH * 2);

#pragma unroll
        for (int k16 = 0; k16 < 32; k16 += 16) {
            uint32_t af[2][4], bf[8][2];
#pragma unroll
            for (int im = 0; im < 2; im++) {
                int m = wm * 32 + im * 16 + l15;
                ldsm_x4(af[im], Asb + (uint32_t)(m * SAH + k16 + lh * 8) * 2);
            }
#pragma unroll
            for (int pr = 0; pr < 4; pr++) {
                int n0 = wn * 64 + pr * 16;
                uint32_t bq[4];
                ldsm_x4t(bq, Bsb + (uint32_t)((k16 + l15) * SBH + n0 + lh * 8) * 2);
                bf[2 * pr][0] = bq[0]; bf[2 * pr][1] = bq[1];
                bf[2 * pr + 1][0] = bq[2]; bf[2 * pr + 1][1] = bq[3];
            }
#pragma unroll
            for (int im = 0; im < 2; im++)
#pragma unroll
                for (int in = 0; in < 8; in++)
                    mma16(acc[im][in], af[im], bf[in][0], bf[in][1]);
        }
    }
#undef LD_NN

    if (HALF_OUT) {
        __half* C = (__half*)Cv + zo * sC1 + zi * sC2;
#pragma unroll
        for (int im = 0; im < 2; im++) {
            int m0 = bm * 128 + wm * 32 + im * 16 + g;
#pragma unroll
            for (int in = 0; in < 8; in++) {
                int n0 = bn * 128 + wn * 64 + in * 8 + t4 * 2;
                __half2 h0 = __floats2half2_rn(acc[im][in][0], acc[im][in][1]);
                __half2 h1 = __floats2half2_rn(acc[im][in][2], acc[im][in][3]);
                *(__half2*)(C + (long long)m0 * N + n0)       = h0;
                *(__half2*)(C + (long long)(m0 + 8) * N + n0) = h1;
            }
        }
    } else {
        float* C = (float*)Cv + zo * sC1 + zi * sC2;
#pragma unroll
        for (int im = 0; im < 2; im++) {
            int m0 = bm * 128 + wm * 32 + im * 16 + g;
            float bv0 = bias ? bias[m0]     : 0.f;
            float bv1 = bias ? bias[m0 + 8] : 0.f;
#pragma unroll
            for (int in = 0; in < 8; in++) {
                int n0 = bn * 128 + wn * 64 + in * 8 + t4 * 2;
                *(float2*)(C + (long long)m0 * N + n0) =
                    make_float2(acc[im][in][0] + bv0, acc[im][in][1] + bv0);
                *(float2*)(C + (long long)(m0 + 8) * N + n0) =
                    make_float2(acc[im][in][2] + bv1, acc[im][in][3] + bv1);
            }
        }
    }
}

// ---------------------------------------------------------------------------
// GEMM2 (NT, split-K 16): ctx_part[slice][bh][e][d] = sum_{n slice} v[e,n]k[d,n]
// ---------------------------------------------------------------------------
__global__ __launch_bounds__(256, 2) void gemm_nt_ctx()
{
    extern __shared__ __half sm[];
    __half* Asm = sm;                    // [NSTG][128][SAH] (v: [e][k])
    __half* Bsm = sm + NSTG * ASTGH;     // [NSTG][128][SAH] (k: [d][k])

    const int slice = blockIdx.x;
    const int bh    = blockIdx.y;
    const int b = bh >> 2, h4 = bh & 3;

    const __half* Ag = g_qkvh + ((long long)b * QKVR + 1024 + h4 * 128) * NPIX;
    const __half* Bg = g_qkvh + ((long long)b * QKVR +  512 + h4 * 128) * NPIX;
    float* C = &g_ctx_part[slice][bh][0][0];

    const int tid  = threadIdx.x;
    const int lane = tid & 31, warp = tid >> 5;
    const int g    = lane >> 2, t4 = lane & 3;
    const int wm   = warp & 3,  wn = warp >> 2;
    const int l15  = lane & 15, lh = lane >> 4;

    const uint32_t asm0 = (uint32_t)__cvta_generic_to_shared(Asm);
    const uint32_t bsm0 = (uint32_t)__cvta_generic_to_shared(Bsm);

#define LD_NT(st, kk) do {                                                       \
    uint32_t ab = asm0 + (uint32_t)(st) * (ASTGH * 2);                           \
    uint32_t bb = bsm0 + (uint32_t)(st) * (ASTGH * 2);                           \
    _Pragma("unroll")                                                            \
    for (int t = 0; t < 2; t++) {                                                \
        int idx = t * 256 + tid;                                                 \
        int row = idx >> 2, ch = idx & 3;                                        \
        uint32_t so = (uint32_t)(row * SAH + ch * 8) * 2;                        \
        cpa16(ab + so, Ag + (long long)row * NPIX + (kk) + ch * 8);              \
        cpa16(bb + so, Bg + (long long)row * NPIX + (kk) + ch * 8);              \
    }                                                                            \
    cp_commit();                                                                 \
} while (0)

    float acc[2][8][4] = {};
    const int kbeg  = slice * (NPIX / KSPLIT);
    const int niter = (NPIX / KSPLIT) >> 5;   // 8

    LD_NT(0, kbeg);
    LD_NT(1, kbeg + 32);
    LD_NT(2, kbeg + 64);

    for (int it = 0; it < niter; ++it) {
        cp_wait<NSTG - 2>();
        __syncthreads();
        const int ls = it + NSTG - 1;
        if (ls < niter) { LD_NT(ls % NSTG, kbeg + ls * 32); }
        else            { cp_commit(); }

        const uint32_t Asb = asm0 + (uint32_t)(it % NSTG) * (ASTGH * 2);
        const uint32_t Bsb = bsm0 + (uint32_t)(it % NSTG) * (ASTGH * 2);

#pragma unroll
        for (int k16 = 0; k16 < 32; k16 += 16) {
            uint32_t af[2][4], bf[8][2];
#pragma unroll
            for (int im = 0; im < 2; im++) {
                int m = wm * 32 + im * 16 + l15;
                ldsm_x4(af[im], Asb + (uint32_t)(m * SAH + k16 + lh * 8) * 2);
            }
#pragma unroll
            for (int pr = 0; pr < 4; pr++) {
                int d0 = wn * 64 + pr * 16;
                uint32_t bq[4];
                ldsm_x4(bq, Bsb + (uint32_t)((d0 + l15) * SAH + k16 + lh * 8) * 2);
                bf[2 * pr][0] = bq[0]; bf[2 * pr][1] = bq[2];
                bf[2 * pr + 1][0] = bq[1]; bf[2 * pr + 1][1] = bq[3];
            }
#pragma unroll
            for (int im = 0; im < 2; im++)
#pragma unroll
                for (int in = 0; in < 8; in++)
                    mma16(acc[im][in], af[im], bf[in][0], bf[in][1]);
        }
    }
#undef LD_NT

#pragma unroll
    for (int im = 0; im < 2; im++) {
        int m0 = wm * 32 + im * 16 + g;
#pragma unroll
        for (int in = 0; in < 8; in++) {
            int n0 = wn * 64 + in * 8 + t4 * 2;
            *(float2*)(C + m0 * 128 + n0)       = make_float2(acc[im][in][0], acc[im][in][1]);
            *(float2*)(C + (m0 + 8) * 128 + n0) = make_float2(acc[im][in][2], acc[im][in][3]);
        }
    }
}

__global__ __launch_bounds__(256) void reduce_ctx()
{
    const long long i = (long long)blockIdx.x * 256 + threadIdx.x;
    const long long total = (long long)BDIM * HEADS * DIMH * DIMH;
    if (i >= total) return;
    const float* p = &g_ctx_part[0][0][0][0];
    float s = 0.f;
#pragma unroll
    for (int k = 0; k < KSPLIT; k++) s += p[(long long)k * total + i];
    (&g_ctxTh[0][0][0])[i] = __float2half_rn(s);
}

// ---------------------------------------------------------------------------
// Softmax over n (4096) on fp16 k rows; register-resident, fp32 math.
// ---------------------------------------------------------------------------
__global__ __launch_bounds__(256) void softmax_k()
{
    const int r = blockIdx.x;
    const int b = r >> 9;
    const int o = 512 + (r & 511);
    __half* row = g_qkvh + ((long long)b * QKVR + o) * NPIX;

    __shared__ float red[8];
    const int tid = threadIdx.x;

    uint4 u0 = ((const uint4*)row)[tid];
    uint4 u1 = ((const uint4*)row)[256 + tid];

    float v[16];
    {
        const __half2* h0 = (const __half2*)&u0;
        const __half2* h1 = (const __half2*)&u1;
#pragma unroll
        for (int i = 0; i < 4; i++) {
            float2 f0 = __half22float2(h0[i]);
            float2 f1 = __half22float2(h1[i]);
            v[2 * i] = f0.x; v[2 * i + 1] = f0.y;
            v[8 + 2 * i] = f1.x; v[8 + 2 * i + 1] = f1.y;
        }
    }

    float mx = v[0];
#pragma unroll
    for (int i = 1; i < 16; i++) mx = fmaxf(mx, v[i]);
#pragma unroll
    for (int off = 16; off; off >>= 1) mx = fmaxf(mx, __shfl_xor_sync(0xffffffffu, mx, off));
    if ((tid & 31) == 0) red[tid >> 5] = mx;
    __syncthreads();
    float m = red[0];
#pragma unroll
    for (int i = 1; i < 8; i++) m = fmaxf(m, red[i]);
    __syncthreads();

    float s = 0.f;
#pragma unroll
    for (int i = 0; i < 16; i++) { v[i] = __expf(v[i] - m); s += v[i]; }
#pragma unroll
    for (int off = 16; off; off >>= 1) s += __shfl_xor_sync(0xffffffffu, s, off);
    if ((tid & 31) == 0) red[tid >> 5] = s;
    __syncthreads();
    float tot = 0.f;
#pragma unroll
    for (int i = 0; i < 8; i++) tot += red[i];
    const float inv = 1.f / tot;

    uint4 w0, w1;
    __half2* o0 = (__half2*)&w0;
    __half2* o1 = (__half2*)&w1;
#pragma unroll
    for (int i = 0; i < 4; i++) {
        o0[i] = __floats2half2_rn(v[2 * i] * inv, v[2 * i + 1] * inv);
        o1[i] = __floats2half2_rn(v[8 + 2 * i] * inv, v[8 + 2 * i + 1] * inv);
    }
    ((uint4*)row)[tid] = w0;
    ((uint4*)row)[256 + tid] = w1;
}

// ---------------------------------------------------------------------------
extern "C" void kernel_launch(void* const* d_in, const int* in_sizes, int n_in,
                              void* d_out, int out_size)
{
    (void)in_sizes; (void)n_in; (void)out_size;
    const float* x     = (const float*)d_in[0];
    const float* w_qkv = (const float*)d_in[1];
    const float* w_out = (const float*)d_in[2];
    const float* b_out = (const float*)d_in[3];
    float* out = (float*)d_out;

    __half *qkv_p, *attn_p, *ctxT_p, *xh_p, *wq_p, *wo_p;
    cudaGetSymbolAddress((void**)&qkv_p,  g_qkvh);
    cudaGetSymbolAddress((void**)&attn_p, g_attnh);
    cudaGetSymbolAddress((void**)&ctxT_p, g_ctxTh);
    cudaGetSymbolAddress((void**)&xh_p,   g_xh);
    cudaGetSymbolAddress((void**)&wq_p,   g_wqh);
    cudaGetSymbolAddress((void**)&wo_p,   g_woh);

    cudaFuncSetAttribute((const void*)gemm_nn<true>,
                         cudaFuncAttributeMaxDynamicSharedMemorySize, SMEM_NN);
    cudaFuncSetAttribute((const void*)gemm_nn<false>,
                         cudaFuncAttributeMaxDynamicSharedMemorySize, SMEM_NN);
    cudaFuncSetAttribute((const void*)gemm_nt_ctx,
                         cudaFuncAttributeMaxDynamicSharedMemorySize, SMEM_NT);

    dim3 blk(256);

    f2h<<<(BDIM * CIN * NPIX / 4 + 255) / 256, blk>>>(x, xh_p, BDIM * CIN * NPIX / 4);
    const int na4 = QKVR * CIN / 4, nb4 = CIN * HID / 4;
    f2h2<<<(na4 + nb4 + 255) / 256, blk>>>(w_qkv, wq_p, na4, w_out, wo_p, nb4);

    // GEMM1: qkv[b] = w_qkv @ x[b]  -> fp16
    gemm_nn<true><<<dim3(NPIX / 128, QKVR / 128, BDIM), blk, SMEM_NN>>>(
        wq_p, 0, 0, CIN,
        xh_p, (long long)CIN * NPIX, 0,
        qkv_p, (long long)QKVR * NPIX, 0,
        nullptr, 1, NPIX, CIN);

    softmax_k<<<BDIM * HEADS * DIMH, blk>>>();

    gemm_nt_ctx<<<dim3(KSPLIT, BDIM * HEADS), blk, SMEM_NT>>>();
    reduce_ctx<<<(BDIM * HEADS * DIMH * DIMH) / 256, blk>>>();

    // GEMM3: attn[b,h] = ctxT[b,h] @ q[b,h]  -> fp16
    gemm_nn<true><<<dim3(NPIX / 128, 1, BDIM * HEADS), blk, SMEM_NN>>>(
        ctxT_p, (long long)HEADS * DIMH * DIMH, (long long)DIMH * DIMH, DIMH,
        qkv_p, (long long)QKVR * NPIX, (long long)DIMH * NPIX,
        attn_p, (long long)HID * NPIX, (long long)DIMH * NPIX,
        nullptr, HEADS, NPIX, DIMH);

    // GEMM4: out[b] = w_out @ attn[b] + b_out  -> fp32
    gemm_nn<false><<<dim3(NPIX / 128, CIN / 128, BDIM), blk, SMEM_NN>>>(
        wo_p, 0, 0, HID,
        attn_p, (long long)HID * NPIX, 0,
        out, (long long)CIN * NPIX, 0,
        b_out, 1, NPIX, HID);
}

// round 14
// speedup vs baseline: 1.5477x; 1.1221x over previous
#include <cuda_runtime.h>
#include <cuda_fp16.h>
#include <cstdint>

// ---------------------------------------------------------------------------
// LinearAttention, fp16 mma.sync m16n8k16 (fp32 accum) + ldmatrix + cp.async.
// R14: associativity refactor — out = (w_out @ ctxT) @ q.
//   M[b,h] = w_out[:,h] @ ctxT[b,h]   (tiny GEMM, 0.27 GFLOP)
//   out[b] = Mcat[b](256x512) @ q[b](512x4096) + bias
// Deletes GEMM3 and the 67MB attn round-trip. GEMM core = R6 exact (3-stage).
// ---------------------------------------------------------------------------

#define BDIM   8
#define CIN    256
#define NPIX   4096
#define HEADS  4
#define DIMH   128
#define HID    512
#define QKVR   1536
#define KSPLIT 8

#define SAH    40                 // A smem stride (halfs): 80B
#define SBH    136                // B smem stride (halfs): 272B
#define ASTGH  (128 * SAH)        // 5120 halfs
#define BSTGH  (32 * SBH)         // 4352 halfs
#define SMEM_NN (3 * (ASTGH + BSTGH) * 2)   // 56832
#define SMEM_NT (3 * 2 * ASTGH * 2)         // 61440

__device__ __half g_qkvh[(size_t)BDIM * QKVR * NPIX];
__device__ float  g_ctx_part[KSPLIT][BDIM * HEADS][DIMH][DIMH];
__device__ __half g_ctxTh[BDIM * HEADS][DIMH][DIMH];
__device__ __half g_M  [BDIM][CIN][HID];          // Mcat: [b][c][h*128+d]
__device__ __half g_xh [(size_t)BDIM * CIN * NPIX];
__device__ __half g_wqh[QKVR * CIN];
__device__ __half g_woh[CIN * HID];

// ---------------- helpers ----------------
__device__ __forceinline__ void cpa16(uint32_t d, const void* s) {
    asm volatile("cp.async.cg.shared.global [%0], [%1], 16;\n" :: "r"(d), "l"(s));
}
__device__ __forceinline__ void cp_commit() { asm volatile("cp.async.commit_group;\n"); }
template<int N> __device__ __forceinline__ void cp_wait() {
    asm volatile("cp.async.wait_group %0;\n" :: "n"(N));
}
__device__ __forceinline__ void ldsm_x4(uint32_t r[4], uint32_t a) {
    asm volatile("ldmatrix.sync.aligned.m8n8.x4.shared.b16 {%0,%1,%2,%3}, [%4];"
        : "=r"(r[0]), "=r"(r[1]), "=r"(r[2]), "=r"(r[3]) : "r"(a));
}
__device__ __forceinline__ void ldsm_x4t(uint32_t r[4], uint32_t a) {
    asm volatile("ldmatrix.sync.aligned.m8n8.x4.trans.shared.b16 {%0,%1,%2,%3}, [%4];"
        : "=r"(r[0]), "=r"(r[1]), "=r"(r[2]), "=r"(r[3]) : "r"(a));
}
__device__ __forceinline__ void mma16(float c[4], const uint32_t a[4], const uint32_t b0, const uint32_t b1) {
    asm volatile(
        "mma.sync.aligned.m16n8k16.row.col.f32.f16.f16.f32 "
        "{%0,%1,%2,%3}, {%4,%5,%6,%7}, {%8,%9}, {%0,%1,%2,%3};"
        : "+f"(c[0]), "+f"(c[1]), "+f"(c[2]), "+f"(c[3])
        : "r"(a[0]), "r"(a[1]), "r"(a[2]), "r"(a[3]), "r"(b0), "r"(b1));
}

// ---------------------------------------------------------------------------
__global__ __launch_bounds__(256) void f2h(
    const float* __restrict__ in, __half* __restrict__ out, int n4)
{
    int i = blockIdx.x * 256 + threadIdx.x;
    if (i < n4) {
        float4 v = ((const float4*)in)[i];
        __half2 h0 = __floats2half2_rn(v.x, v.y);
        __half2 h1 = __floats2half2_rn(v.z, v.w);
        uint2 u;
        u.x = *(uint32_t*)&h0;
        u.y = *(uint32_t*)&h1;
        ((uint2*)out)[i] = u;
    }
}
__global__ __launch_bounds__(256) void f2h2(
    const float* __restrict__ a, __half* __restrict__ oa, int na4,
    const float* __restrict__ b, __half* __restrict__ ob, int nb4)
{
    int i = blockIdx.x * 256 + threadIdx.x;
    const float* src; __half* dst; int j;
    if (i < na4) { src = a; dst = oa; j = i; }
    else         { j = i - na4; if (j >= nb4) return; src = b; dst = ob; }
    float4 v = ((const float4*)src)[j];
    __half2 h0 = __floats2half2_rn(v.x, v.y);
    __half2 h1 = __floats2half2_rn(v.z, v.w);
    uint2 u;
    u.x = *(uint32_t*)&h0;
    u.y = *(uint32_t*)&h1;
    ((uint2*)dst)[j] = u;
}

// ---------------------------------------------------------------------------
// NN GEMM fp16: C = A[M,K]@B[K,N] (+bias). 128x128 tile, BK=32, 3-stage.
// ldb = N (B row stride); ldc independent (C row stride).
// ---------------------------------------------------------------------------
template<bool HALF_OUT>
__global__ __launch_bounds__(256, 2) void gemm_nn(
    const __half* __restrict__ A, long long sA1, long long sA2, int lda,
    const __half* __restrict__ B, long long sB1, long long sB2,
    void*         __restrict__ Cv, long long sC1, long long sC2, int ldc,
    const float* __restrict__ bias,
    int zdiv, int N, int K)
{
    extern __shared__ __half sm[];
    __half* Asm = sm;                 // [3][128][SAH]
    __half* Bsm = sm + 3 * ASTGH;     // [3][32][SBH]

    const int bm = blockIdx.y, bn = blockIdx.x;
    const int zo = blockIdx.z / zdiv, zi = blockIdx.z % zdiv;
    A += zo * sA1 + zi * sA2;
    B += zo * sB1 + zi * sB2;

    const int tid  = threadIdx.x;
    const int lane = tid & 31, warp = tid >> 5;
    const int g    = lane >> 2, t4 = lane & 3;
    const int wm   = warp & 3,  wn = warp >> 2;
    const int l15  = lane & 15, lh = lane >> 4;

    const __half* Ag = A + (long long)bm * 128 * lda;
    const __half* Bg = B + bn * 128;

    const uint32_t asm0 = (uint32_t)__cvta_generic_to_shared(Asm);
    const uint32_t bsm0 = (uint32_t)__cvta_generic_to_shared(Bsm);

#define LD_NN(st, kk) do {                                                       \
    uint32_t ab = asm0 + (uint32_t)(st) * (ASTGH * 2);                           \
    uint32_t bb = bsm0 + (uint32_t)(st) * (BSTGH * 2);                           \
    _Pragma("unroll")                                                            \
    for (int t = 0; t < 2; t++) {                                                \
        int idx = t * 256 + tid;                                                 \
        int row = idx >> 2, ch = idx & 3;                                        \
        cpa16(ab + (uint32_t)(row * SAH + ch * 8) * 2,                           \
              Ag + (long long)row * lda + (kk) + ch * 8);                        \
        int kr = idx >> 4, nc = idx & 15;                                        \
        cpa16(bb + (uint32_t)(kr * SBH + nc * 8) * 2,                            \
              Bg + (long long)((kk) + kr) * N + nc * 8);                         \
    }                                                                            \
    cp_commit();                                                                 \
} while (0)

    float acc[2][8][4] = {};
    const int niter = K >> 5;

    LD_NN(0, 0);
    LD_NN(1, 32);

    for (int it = 0; it < niter; ++it) {
        cp_wait<1>();
        __syncthreads();
        const int ls = it + 2;
        if (ls < niter) { LD_NN(ls % 3, ls * 32); }
        else            { cp_commit(); }

        const uint32_t Asb = asm0 + (uint32_t)(it % 3) * (ASTGH * 2);
        const uint32_t Bsb = bsm0 + (uint32_t)(it % 3) * (BSTGH * 2);

#pragma unroll
        for (int k16 = 0; k16 < 32; k16 += 16) {
            uint32_t af[2][4], bf[8][2];
#pragma unroll
            for (int im = 0; im < 2; im++) {
                int m = wm * 32 + im * 16 + l15;
                ldsm_x4(af[im], Asb + (uint32_t)(m * SAH + k16 + lh * 8) * 2);
            }
#pragma unroll
            for (int pr = 0; pr < 4; pr++) {
                int n0 = wn * 64 + pr * 16;
                uint32_t bq[4];
                ldsm_x4t(bq, Bsb + (uint32_t)((k16 + l15) * SBH + n0 + lh * 8) * 2);
                bf[2 * pr][0] = bq[0]; bf[2 * pr][1] = bq[1];
                bf[2 * pr + 1][0] = bq[2]; bf[2 * pr + 1][1] = bq[3];
            }
#pragma unroll
            for (int im = 0; im < 2; im++)
#pragma unroll
                for (int in = 0; in < 8; in++)
                    mma16(acc[im][in], af[im], bf[in][0], bf[in][1]);
        }
    }
#undef LD_NN

    if (HALF_OUT) {
        __half* C = (__half*)Cv + zo * sC1 + zi * sC2;
#pragma unroll
        for (int im = 0; im < 2; im++) {
            int m0 = bm * 128 + wm * 32 + im * 16 + g;
#pragma unroll
            for (int in = 0; in < 8; in++) {
                int n0 = bn * 128 + wn * 64 + in * 8 + t4 * 2;
                __half2 h0 = __floats2half2_rn(acc[im][in][0], acc[im][in][1]);
                __half2 h1 = __floats2half2_rn(acc[im][in][2], acc[im][in][3]);
                *(__half2*)(C + (long long)m0 * ldc + n0)       = h0;
                *(__half2*)(C + (long long)(m0 + 8) * ldc + n0) = h1;
            }
        }
    } else {
        float* C = (float*)Cv + zo * sC1 + zi * sC2;
#pragma unroll
        for (int im = 0; im < 2; im++) {
            int m0 = bm * 128 + wm * 32 + im * 16 + g;
            float bv0 = bias ? bias[m0]     : 0.f;
            float bv1 = bias ? bias[m0 + 8] : 0.f;
#pragma unroll
            for (int in = 0; in < 8; in++) {
                int n0 = bn * 128 + wn * 64 + in * 8 + t4 * 2;
                *(float2*)(C + (long long)m0 * ldc + n0) =
                    make_float2(acc[im][in][0] + bv0, acc[im][in][1] + bv0);
                *(float2*)(C + (long long)(m0 + 8) * ldc + n0) =
                    make_float2(acc[im][in][2] + bv1, acc[im][in][3] + bv1);
            }
        }
    }
}

// ---------------------------------------------------------------------------
// GEMM2 (NT, split-K): ctx_part[slice][bh][e][d] = sum_{n slice} v[e,n]k[d,n]
// ---------------------------------------------------------------------------
__global__ __launch_bounds__(256, 2) void gemm_nt_ctx()
{
    extern __shared__ __half sm[];
    __half* Asm = sm;                 // [3][128][SAH] (v: [e][k])
    __half* Bsm = sm + 3 * ASTGH;     // [3][128][SAH] (k: [d][k])

    const int slice = blockIdx.x;
    const int bh    = blockIdx.y;
    const int b = bh >> 2, h4 = bh & 3;

    const __half* Ag = g_qkvh + ((long long)b * QKVR + 1024 + h4 * 128) * NPIX;
    const __half* Bg = g_qkvh + ((long long)b * QKVR +  512 + h4 * 128) * NPIX;
    float* C = &g_ctx_part[slice][bh][0][0];

    const int tid  = threadIdx.x;
    const int lane = tid & 31, warp = tid >> 5;
    const int g    = lane >> 2, t4 = lane & 3;
    const int wm   = warp & 3,  wn = warp >> 2;
    const int l15  = lane & 15, lh = lane >> 4;

    const uint32_t asm0 = (uint32_t)__cvta_generic_to_shared(Asm);
    const uint32_t bsm0 = (uint32_t)__cvta_generic_to_shared(Bsm);

#define LD_NT(st, kk) do {                                                       \
    uint32_t ab = asm0 + (uint32_t)(st) * (ASTGH * 2);                           \
    uint32_t bb = bsm0 + (uint32_t)(st) * (ASTGH * 2);                           \
    _Pragma("unroll")                                                            \
    for (int t = 0; t < 2; t++) {                                                \
        int idx = t * 256 + tid;                                                 \
        int row = idx >> 2, ch = idx & 3;                                        \
        uint32_t so = (uint32_t)(row * SAH + ch * 8) * 2;                        \
        cpa16(ab + so, Ag + (long long)row * NPIX + (kk) + ch * 8);              \
        cpa16(bb + so, Bg + (long long)row * NPIX + (kk) + ch * 8);              \
    }                                                                            \
    cp_commit();                                                                 \
} while (0)

    float acc[2][8][4] = {};
    const int kbeg  = slice * (NPIX / KSPLIT);
    const int niter = (NPIX / KSPLIT) >> 5;   // 16

    LD_NT(0, kbeg);
    LD_NT(1, kbeg + 32);

    for (int it = 0; it < niter; ++it) {
        cp_wait<1>();
        __syncthreads();
        const int ls = it + 2;
        if (ls < niter) { LD_NT(ls % 3, kbeg + ls * 32); }
        else            { cp_commit(); }

        const uint32_t Asb = asm0 + (uint32_t)(it % 3) * (ASTGH * 2);
        const uint32_t Bsb = bsm0 + (uint32_t)(it % 3) * (ASTGH * 2);

#pragma unroll
        for (int k16 = 0; k16 < 32; k16 += 16) {
            uint32_t af[2][4], bf[8][2];
#pragma unroll
            for (int im = 0; im < 2; im++) {
                int m = wm * 32 + im * 16 + l15;
                ldsm_x4(af[im], Asb + (uint32_t)(m * SAH + k16 + lh * 8) * 2);
            }
#pragma unroll
            for (int pr = 0; pr < 4; pr++) {
                int d0 = wn * 64 + pr * 16;
                uint32_t bq[4];
                ldsm_x4(bq, Bsb + (uint32_t)((d0 + l15) * SAH + k16 + lh * 8) * 2);
                bf[2 * pr][0] = bq[0]; bf[2 * pr][1] = bq[2];
                bf[2 * pr + 1][0] = bq[1]; bf[2 * pr + 1][1] = bq[3];
            }
#pragma unroll
            for (int im = 0; im < 2; im++)
#pragma unroll
                for (int in = 0; in < 8; in++)
                    mma16(acc[im][in], af[im], bf[in][0], bf[in][1]);
        }
    }
#undef LD_NT

#pragma unroll
    for (int im = 0; im < 2; im++) {
        int m0 = wm * 32 + im * 16 + g;
#pragma unroll
        for (int in = 0; in < 8; in++) {
            int n0 = wn * 64 + in * 8 + t4 * 2;
            *(float2*)(C + m0 * 128 + n0)       = make_float2(acc[im][in][0], acc[im][in][1]);
            *(float2*)(C + (m0 + 8) * 128 + n0) = make_float2(acc[im][in][2], acc[im][in][3]);
        }
    }
}

__global__ __launch_bounds__(256) void reduce_ctx()
{
    const long long i = (long long)blockIdx.x * 256 + threadIdx.x;
    const long long total = (long long)BDIM * HEADS * DIMH * DIMH;
    if (i >= total) return;
    const float* p = &g_ctx_part[0][0][0][0];
    float s = 0.f;
#pragma unroll
    for (int k = 0; k < KSPLIT; k++) s += p[(long long)k * total + i];
    (&g_ctxTh[0][0][0])[i] = __float2half_rn(s);
}

// ---------------------------------------------------------------------------
// Softmax over n (4096) on fp16 k rows; register-resident, fp32 math.
// ---------------------------------------------------------------------------
__global__ __launch_bounds__(256) void softmax_k()
{
    const int r = blockIdx.x;
    const int b = r >> 9;
    const int o = 512 + (r & 511);
    __half* row = g_qkvh + ((long long)b * QKVR + o) * NPIX;

    __shared__ float red[8];
    const int tid = threadIdx.x;

    uint4 u0 = ((const uint4*)row)[tid];
    uint4 u1 = ((const uint4*)row)[256 + tid];

    float v[16];
    {
        const __half2* h0 = (const __half2*)&u0;
        const __half2* h1 = (const __half2*)&u1;
#pragma unroll
        for (int i = 0; i < 4; i++) {
            float2 f0 = __half22float2(h0[i]);
            float2 f1 = __half22float2(h1[i]);
            v[2 * i] = f0.x; v[2 * i + 1] = f0.y;
            v[8 + 2 * i] = f1.x; v[8 + 2 * i + 1] = f1.y;
        }
    }

    float mx = v[0];
#pragma unroll
    for (int i = 1; i < 16; i++) mx = fmaxf(mx, v[i]);
#pragma unroll
    for (int off = 16; off; off >>= 1) mx = fmaxf(mx, __shfl_xor_sync(0xffffffffu, mx, off));
    if ((tid & 31) == 0) red[tid >> 5] = mx;
    __syncthreads();
    float m = red[0];
#pragma unroll
    for (int i = 1; i < 8; i++) m = fmaxf(m, red[i]);
    __syncthreads();

    float s = 0.f;
#pragma unroll
    for (int i = 0; i < 16; i++) { v[i] = __expf(v[i] - m); s += v[i]; }
#pragma unroll
    for (int off = 16; off; off >>= 1) s += __shfl_xor_sync(0xffffffffu, s, off);
    if ((tid & 31) == 0) red[tid >> 5] = s;
    __syncthreads();
    float tot = 0.f;
#pragma unroll
    for (int i = 0; i < 8; i++) tot += red[i];
    const float inv = 1.f / tot;

    uint4 w0, w1;
    __half2* o0 = (__half2*)&w0;
    __half2* o1 = (__half2*)&w1;
#pragma unroll
    for (int i = 0; i < 4; i++) {
        o0[i] = __floats2half2_rn(v[2 * i] * inv, v[2 * i + 1] * inv);
        o1[i] = __floats2half2_rn(v[8 + 2 * i] * inv, v[8 + 2 * i + 1] * inv);
    }
    ((uint4*)row)[tid] = w0;
    ((uint4*)row)[256 + tid] = w1;
}

// ---------------------------------------------------------------------------
extern "C" void kernel_launch(void* const* d_in, const int* in_sizes, int n_in,
                              void* d_out, int out_size)
{
    (void)in_sizes; (void)n_in; (void)out_size;
    const float* x     = (const float*)d_in[0];
    const float* w_qkv = (const float*)d_in[1];
    const float* w_out = (const float*)d_in[2];
    const float* b_out = (const float*)d_in[3];
    float* out = (float*)d_out;

    __half *qkv_p, *ctxT_p, *M_p, *xh_p, *wq_p, *wo_p;
    cudaGetSymbolAddress((void**)&qkv_p,  g_qkvh);
    cudaGetSymbolAddress((void**)&ctxT_p, g_ctxTh);
    cudaGetSymbolAddress((void**)&M_p,    g_M);
    cudaGetSymbolAddress((void**)&xh_p,   g_xh);
    cudaGetSymbolAddress((void**)&wq_p,   g_wqh);
    cudaGetSymbolAddress((void**)&wo_p,   g_woh);

    cudaFuncSetAttribute((const void*)gemm_nn<true>,
                         cudaFuncAttributeMaxDynamicSharedMemorySize, SMEM_NN);
    cudaFuncSetAttribute((const void*)gemm_nn<false>,
                         cudaFuncAttributeMaxDynamicSharedMemorySize, SMEM_NN);
    cudaFuncSetAttribute((const void*)gemm_nt_ctx,
                         cudaFuncAttributeMaxDynamicSharedMemorySize, SMEM_NT);

    dim3 blk(256);

    f2h<<<(BDIM * CIN * NPIX / 4 + 255) / 256, blk>>>(x, xh_p, BDIM * CIN * NPIX / 4);
    const int na4 = QKVR * CIN / 4, nb4 = CIN * HID / 4;
    f2h2<<<(na4 + nb4 + 255) / 256, blk>>>(w_qkv, wq_p, na4, w_out, wo_p, nb4);

    // GEMM1: qkv[b] = w_qkv @ x[b]  -> fp16
    gemm_nn<true><<<dim3(NPIX / 128, QKVR / 128, BDIM), blk, SMEM_NN>>>(
        wq_p, 0, 0, CIN,
        xh_p, (long long)CIN * NPIX, 0,
        qkv_p, (long long)QKVR * NPIX, 0, NPIX,
        nullptr, 1, NPIX, CIN);

    softmax_k<<<BDIM * HEADS * DIMH, blk>>>();

    gemm_nt_ctx<<<dim3(KSPLIT, BDIM * HEADS), blk, SMEM_NT>>>();
    reduce_ctx<<<(BDIM * HEADS * DIMH * DIMH) / 256, blk>>>();

    // M-GEMM: M[b,h](256x128) = w_out[:, h*128:(h+1)*128] @ ctxT[b,h]
    //   z = b*4+h: A = wo_p + h*128 (lda 512); B = ctxT + (b*4+h)*128*128;
    //   C = Mcat + b*256*512 + h*128 (ldc 512)
    gemm_nn<true><<<dim3(1, CIN / 128, BDIM * HEADS), blk, SMEM_NN>>>(
        wo_p, 0, DIMH, HID,
        ctxT_p, (long long)HEADS * DIMH * DIMH, (long long)DIMH * DIMH,
        M_p, (long long)CIN * HID, DIMH, HID,
        nullptr, HEADS, DIMH, DIMH);

    // Final: out[b] = Mcat[b](256x512) @ q_rows[b](512x4096) + bias  -> fp32
    gemm_nn<false><<<dim3(NPIX / 128, CIN / 128, BDIM), blk, SMEM_NN>>>(
        M_p, (long long)CIN * HID, 0, HID,
        qkv_p, (long long)QKVR * NPIX, 0,
        out, (long long)CIN * NPIX, 0, NPIX,
        b_out, 1, NPIX, HID);
}

// round 15
// speedup vs baseline: 1.8832x; 1.2168x over previous
#include <cuda_runtime.h>
#include <cuda_fp16.h>
#include <cstdint>

// ---------------------------------------------------------------------------
// LinearAttention, fp16 mma.sync m16n8k16 (fp32 accum) + ldmatrix + cp.async.
// R15: double associativity refactor.
//   out = w_out @ ((k_sm @ v^T)^T-chain @ q) = ((w_out@ctxT) @ w_q) @ x
//   GEMM1 computes only k,v (M=1024);  M = w_out@ctxT;  W2 = Mcat@w_q;
//   out = W2 @ x + bias.  GEMM core = R6/R14 exact.
// ---------------------------------------------------------------------------

#define BDIM   8
#define CIN    256
#define NPIX   4096
#define HEADS  4
#define DIMH   128
#define HID    512
#define QKVR   1536
#define KSPLIT 8

#define SAH    40                 // A smem stride (halfs): 80B
#define SBH    136                // B smem stride (halfs): 272B
#define ASTGH  (128 * SAH)        // 5120 halfs
#define BSTGH  (32 * SBH)         // 4352 halfs
#define SMEM_NN (3 * (ASTGH + BSTGH) * 2)   // 56832
#define SMEM_NT (3 * 2 * ASTGH * 2)         // 61440

__device__ __half g_qkvh[(size_t)BDIM * QKVR * NPIX];   // only rows 512.. used
__device__ float  g_ctx_part[KSPLIT][BDIM * HEADS][DIMH][DIMH];
__device__ __half g_ctxTh[BDIM * HEADS][DIMH][DIMH];
__device__ __half g_M  [BDIM][CIN][HID];          // Mcat: [b][c][h*128+d]
__device__ __half g_W2 [BDIM][CIN][CIN];          // W2 = Mcat @ w_q
__device__ __half g_xh [(size_t)BDIM * CIN * NPIX];
__device__ __half g_wqh[QKVR * CIN];
__device__ __half g_woh[CIN * HID];

// ---------------- helpers ----------------
__device__ __forceinline__ void cpa16(uint32_t d, const void* s) {
    asm volatile("cp.async.cg.shared.global [%0], [%1], 16;\n" :: "r"(d), "l"(s));
}
__device__ __forceinline__ void cp_commit() { asm volatile("cp.async.commit_group;\n"); }
template<int N> __device__ __forceinline__ void cp_wait() {
    asm volatile("cp.async.wait_group %0;\n" :: "n"(N));
}
__device__ __forceinline__ void ldsm_x4(uint32_t r[4], uint32_t a) {
    asm volatile("ldmatrix.sync.aligned.m8n8.x4.shared.b16 {%0,%1,%2,%3}, [%4];"
        : "=r"(r[0]), "=r"(r[1]), "=r"(r[2]), "=r"(r[3]) : "r"(a));
}
__device__ __forceinline__ void ldsm_x4t(uint32_t r[4], uint32_t a) {
    asm volatile("ldmatrix.sync.aligned.m8n8.x4.trans.shared.b16 {%0,%1,%2,%3}, [%4];"
        : "=r"(r[0]), "=r"(r[1]), "=r"(r[2]), "=r"(r[3]) : "r"(a));
}
__device__ __forceinline__ void mma16(float c[4], const uint32_t a[4], const uint32_t b0, const uint32_t b1) {
    asm volatile(
        "mma.sync.aligned.m16n8k16.row.col.f32.f16.f16.f32 "
        "{%0,%1,%2,%3}, {%4,%5,%6,%7}, {%8,%9}, {%0,%1,%2,%3};"
        : "+f"(c[0]), "+f"(c[1]), "+f"(c[2]), "+f"(c[3])
        : "r"(a[0]), "r"(a[1]), "r"(a[2]), "r"(a[3]), "r"(b0), "r"(b1));
}

// ---------------------------------------------------------------------------
__global__ __launch_bounds__(256) void f2h(
    const float* __restrict__ in, __half* __restrict__ out, int n4)
{
    int i = blockIdx.x * 256 + threadIdx.x;
    if (i < n4) {
        float4 v = ((const float4*)in)[i];
        __half2 h0 = __floats2half2_rn(v.x, v.y);
        __half2 h1 = __floats2half2_rn(v.z, v.w);
        uint2 u;
        u.x = *(uint32_t*)&h0;
        u.y = *(uint32_t*)&h1;
        ((uint2*)out)[i] = u;
    }
}
__global__ __launch_bounds__(256) void f2h2(
    const float* __restrict__ a, __half* __restrict__ oa, int na4,
    const float* __restrict__ b, __half* __restrict__ ob, int nb4)
{
    int i = blockIdx.x * 256 + threadIdx.x;
    const float* src; __half* dst; int j;
    if (i < na4) { src = a; dst = oa; j = i; }
    else         { j = i - na4; if (j >= nb4) return; src = b; dst = ob; }
    float4 v = ((const float4*)src)[j];
    __half2 h0 = __floats2half2_rn(v.x, v.y);
    __half2 h1 = __floats2half2_rn(v.z, v.w);
    uint2 u;
    u.x = *(uint32_t*)&h0;
    u.y = *(uint32_t*)&h1;
    ((uint2*)dst)[j] = u;
}

// ---------------------------------------------------------------------------
// NN GEMM fp16: C = A[M,K]@B[K,N] (+bias). 128x128 tile, BK=32, 3-stage.
// B row stride = N; C row stride = ldc.
// ---------------------------------------------------------------------------
template<bool HALF_OUT>
__global__ __launch_bounds__(256, 2) void gemm_nn(
    const __half* __restrict__ A, long long sA1, long long sA2, int lda,
    const __half* __restrict__ B, long long sB1, long long sB2,
    void*         __restrict__ Cv, long long sC1, long long sC2, int ldc,
    const float* __restrict__ bias,
    int zdiv, int N, int K)
{
    extern __shared__ __half sm[];
    __half* Asm = sm;                 // [3][128][SAH]
    __half* Bsm = sm + 3 * ASTGH;     // [3][32][SBH]

    const int bm = blockIdx.y, bn = blockIdx.x;
    const int zo = blockIdx.z / zdiv, zi = blockIdx.z % zdiv;
    A += zo * sA1 + zi * sA2;
    B += zo * sB1 + zi * sB2;

    const int tid  = threadIdx.x;
    const int lane = tid & 31, warp = tid >> 5;
    const int g    = lane >> 2, t4 = lane & 3;
    const int wm   = warp & 3,  wn = warp >> 2;
    const int l15  = lane & 15, lh = lane >> 4;

    const __half* Ag = A + (long long)bm * 128 * lda;
    const __half* Bg = B + bn * 128;

    const uint32_t asm0 = (uint32_t)__cvta_generic_to_shared(Asm);
    const uint32_t bsm0 = (uint32_t)__cvta_generic_to_shared(Bsm);

#define LD_NN(st, kk) do {                                                       \
    uint32_t ab = asm0 + (uint32_t)(st) * (ASTGH * 2);                           \
    uint32_t bb = bsm0 + (uint32_t)(st) * (BSTGH * 2);                           \
    _Pragma("unroll")                                                            \
    for (int t = 0; t < 2; t++) {                                                \
        int idx = t * 256 + tid;                                                 \
        int row = idx >> 2, ch = idx & 3;                                        \
        cpa16(ab + (uint32_t)(row * SAH + ch * 8) * 2,                           \
              Ag + (long long)row * lda + (kk) + ch * 8);                        \
        int kr = idx >> 4, nc = idx & 15;                                        \
        cpa16(bb + (uint32_t)(kr * SBH + nc * 8) * 2,                            \
              Bg + (long long)((kk) + kr) * N + nc * 8);                         \
    }                                                                            \
    cp_commit();                                                                 \
} while (0)

    float acc[2][8][4] = {};
    const int niter = K >> 5;

    LD_NN(0, 0);
    LD_NN(1, 32);

    for (int it = 0; it < niter; ++it) {
        cp_wait<1>();
        __syncthreads();
        const int ls = it + 2;
        if (ls < niter) { LD_NN(ls % 3, ls * 32); }
        else            { cp_commit(); }

        const uint32_t Asb = asm0 + (uint32_t)(it % 3) * (ASTGH * 2);
        const uint32_t Bsb = bsm0 + (uint32_t)(it % 3) * (BSTGH * 2);

#pragma unroll
        for (int k16 = 0; k16 < 32; k16 += 16) {
            uint32_t af[2][4], bf[8][2];
#pragma unroll
            for (int im = 0; im < 2; im++) {
                int m = wm * 32 + im * 16 + l15;
                ldsm_x4(af[im], Asb + (uint32_t)(m * SAH + k16 + lh * 8) * 2);
            }
#pragma unroll
            for (int pr = 0; pr < 4; pr++) {
                int n0 = wn * 64 + pr * 16;
                uint32_t bq[4];
                ldsm_x4t(bq, Bsb + (uint32_t)((k16 + l15) * SBH + n0 + lh * 8) * 2);
                bf[2 * pr][0] = bq[0]; bf[2 * pr][1] = bq[1];
                bf[2 * pr + 1][0] = bq[2]; bf[2 * pr + 1][1] = bq[3];
            }
#pragma unroll
            for (int im = 0; im < 2; im++)
#pragma unroll
                for (int in = 0; in < 8; in++)
                    mma16(acc[im][in], af[im], bf[in][0], bf[in][1]);
        }
    }
#undef LD_NN

    if (HALF_OUT) {
        __half* C = (__half*)Cv + zo * sC1 + zi * sC2;
#pragma unroll
        for (int im = 0; im < 2; im++) {
            int m0 = bm * 128 + wm * 32 + im * 16 + g;
#pragma unroll
            for (int in = 0; in < 8; in++) {
                int n0 = bn * 128 + wn * 64 + in * 8 + t4 * 2;
                __half2 h0 = __floats2half2_rn(acc[im][in][0], acc[im][in][1]);
                __half2 h1 = __floats2half2_rn(acc[im][in][2], acc[im][in][3]);
                *(__half2*)(C + (long long)m0 * ldc + n0)       = h0;
                *(__half2*)(C + (long long)(m0 + 8) * ldc + n0) = h1;
            }
        }
    } else {
        float* C = (float*)Cv + zo * sC1 + zi * sC2;
#pragma unroll
        for (int im = 0; im < 2; im++) {
            int m0 = bm * 128 + wm * 32 + im * 16 + g;
            float bv0 = bias ? bias[m0]     : 0.f;
            float bv1 = bias ? bias[m0 + 8] : 0.f;
#pragma unroll
            for (int in = 0; in < 8; in++) {
                int n0 = bn * 128 + wn * 64 + in * 8 + t4 * 2;
                *(float2*)(C + (long long)m0 * ldc + n0) =
                    make_float2(acc[im][in][0] + bv0, acc[im][in][1] + bv0);
                *(float2*)(C + (long long)(m0 + 8) * ldc + n0) =
                    make_float2(acc[im][in][2] + bv1, acc[im][in][3] + bv1);
            }
        }
    }
}

// ---------------------------------------------------------------------------
// GEMM2 (NT, split-K): ctx_part[slice][bh][e][d] = sum_{n slice} v[e,n]k[d,n]
// ---------------------------------------------------------------------------
__global__ __launch_bounds__(256, 2) void gemm_nt_ctx()
{
    extern __shared__ __half sm[];
    __half* Asm = sm;                 // [3][128][SAH] (v: [e][k])
    __half* Bsm = sm + 3 * ASTGH;     // [3][128][SAH] (k: [d][k])

    const int slice = blockIdx.x;
    const int bh    = blockIdx.y;
    const int b = bh >> 2, h4 = bh & 3;

    const __half* Ag = g_qkvh + ((long long)b * QKVR + 1024 + h4 * 128) * NPIX;
    const __half* Bg = g_qkvh + ((long long)b * QKVR +  512 + h4 * 128) * NPIX;
    float* C = &g_ctx_part[slice][bh][0][0];

    const int tid  = threadIdx.x;
    const int lane = tid & 31, warp = tid >> 5;
    const int g    = lane >> 2, t4 = lane & 3;
    const int wm   = warp & 3,  wn = warp >> 2;
    const int l15  = lane & 15, lh = lane >> 4;

    const uint32_t asm0 = (uint32_t)__cvta_generic_to_shared(Asm);
    const uint32_t bsm0 = (uint32_t)__cvta_generic_to_shared(Bsm);

#define LD_NT(st, kk) do {                                                       \
    uint32_t ab = asm0 + (uint32_t)(st) * (ASTGH * 2);                           \
    uint32_t bb = bsm0 + (uint32_t)(st) * (ASTGH * 2);                           \
    _Pragma("unroll")                                                            \
    for (int t = 0; t < 2; t++) {                                                \
        int idx = t * 256 + tid;                                                 \
        int row = idx >> 2, ch = idx & 3;                                        \
        uint32_t so = (uint32_t)(row * SAH + ch * 8) * 2;                        \
        cpa16(ab + so, Ag + (long long)row * NPIX + (kk) + ch * 8);              \
        cpa16(bb + so, Bg + (long long)row * NPIX + (kk) + ch * 8);              \
    }                                                                            \
    cp_commit();                                                                 \
} while (0)

    float acc[2][8][4] = {};
    const int kbeg  = slice * (NPIX / KSPLIT);
    const int niter = (NPIX / KSPLIT) >> 5;   // 16

    LD_NT(0, kbeg);
    LD_NT(1, kbeg + 32);

    for (int it = 0; it < niter; ++it) {
        cp_wait<1>();
        __syncthreads();
        const int ls = it + 2;
        if (ls < niter) { LD_NT(ls % 3, kbeg + ls * 32); }
        else            { cp_commit(); }

        const uint32_t Asb = asm0 + (uint32_t)(it % 3) * (ASTGH * 2);
        const uint32_t Bsb = bsm0 + (uint32_t)(it % 3) * (ASTGH * 2);

#pragma unroll
        for (int k16 = 0; k16 < 32; k16 += 16) {
            uint32_t af[2][4], bf[8][2];
#pragma unroll
            for (int im = 0; im < 2; im++) {
                int m = wm * 32 + im * 16 + l15;
                ldsm_x4(af[im], Asb + (uint32_t)(m * SAH + k16 + lh * 8) * 2);
            }
#pragma unroll
            for (int pr = 0; pr < 4; pr++) {
                int d0 = wn * 64 + pr * 16;
                uint32_t bq[4];
                ldsm_x4(bq, Bsb + (uint32_t)((d0 + l15) * SAH + k16 + lh * 8) * 2);
                bf[2 * pr][0] = bq[0]; bf[2 * pr][1] = bq[2];
                bf[2 * pr + 1][0] = bq[1]; bf[2 * pr + 1][1] = bq[3];
            }
#pragma unroll
            for (int im = 0; im < 2; im++)
#pragma unroll
                for (int in = 0; in < 8; in++)
                    mma16(acc[im][in], af[im], bf[in][0], bf[in][1]);
        }
    }
#undef LD_NT

#pragma unroll
    for (int im = 0; im < 2; im++) {
        int m0 = wm * 32 + im * 16 + g;
#pragma unroll
        for (int in = 0; in < 8; in++) {
            int n0 = wn * 64 + in * 8 + t4 * 2;
            *(float2*)(C + m0 * 128 + n0)       = make_float2(acc[im][in][0], acc[im][in][1]);
            *(float2*)(C + (m0 + 8) * 128 + n0) = make_float2(acc[im][in][2], acc[im][in][3]);
        }
    }
}

__global__ __launch_bounds__(256) void reduce_ctx()
{
    const long long i = (long long)blockIdx.x * 256 + threadIdx.x;
    const long long total = (long long)BDIM * HEADS * DIMH * DIMH;
    if (i >= total) return;
    const float* p = &g_ctx_part[0][0][0][0];
    float s = 0.f;
#pragma unroll
    for (int k = 0; k < KSPLIT; k++) s += p[(long long)k * total + i];
    (&g_ctxTh[0][0][0])[i] = __float2half_rn(s);
}

// ---------------------------------------------------------------------------
// Softmax over n (4096) on fp16 k rows; register-resident, fp32 math.
// ---------------------------------------------------------------------------
__global__ __launch_bounds__(256) void softmax_k()
{
    const int r = blockIdx.x;
    const int b = r >> 9;
    const int o = 512 + (r & 511);
    __half* row = g_qkvh + ((long long)b * QKVR + o) * NPIX;

    __shared__ float red[8];
    const int tid = threadIdx.x;

    uint4 u0 = ((const uint4*)row)[tid];
    uint4 u1 = ((const uint4*)row)[256 + tid];

    float v[16];
    {
        const __half2* h0 = (const __half2*)&u0;
        const __half2* h1 = (const __half2*)&u1;
#pragma unroll
        for (int i = 0; i < 4; i++) {
            float2 f0 = __half22float2(h0[i]);
            float2 f1 = __half22float2(h1[i]);
            v[2 * i] = f0.x; v[2 * i + 1] = f0.y;
            v[8 + 2 * i] = f1.x; v[8 + 2 * i + 1] = f1.y;
        }
    }

    float mx = v[0];
#pragma unroll
    for (int i = 1; i < 16; i++) mx = fmaxf(mx, v[i]);
#pragma unroll
    for (int off = 16; off; off >>= 1) mx = fmaxf(mx, __shfl_xor_sync(0xffffffffu, mx, off));
    if ((tid & 31) == 0) red[tid >> 5] = mx;
    __syncthreads();
    float m = red[0];
#pragma unroll
    for (int i = 1; i < 8; i++) m = fmaxf(m, red[i]);
    __syncthreads();

    float s = 0.f;
#pragma unroll
    for (int i = 0; i < 16; i++) { v[i] = __expf(v[i] - m); s += v[i]; }
#pragma unroll
    for (int off = 16; off; off >>= 1) s += __shfl_xor_sync(0xffffffffu, s, off);
    if ((tid & 31) == 0) red[tid >> 5] = s;
    __syncthreads();
    float tot = 0.f;
#pragma unroll
    for (int i = 0; i < 8; i++) tot += red[i];
    const float inv = 1.f / tot;

    uint4 w0, w1;
    __half2* o0 = (__half2*)&w0;
    __half2* o1 = (__half2*)&w1;
#pragma unroll
    for (int i = 0; i < 4; i++) {
        o0[i] = __floats2half2_rn(v[2 * i] * inv, v[2 * i + 1] * inv);
        o1[i] = __floats2half2_rn(v[8 + 2 * i] * inv, v[8 + 2 * i + 1] * inv);
    }
    ((uint4*)row)[tid] = w0;
    ((uint4*)row)[256 + tid] = w1;
}

// ---------------------------------------------------------------------------
extern "C" void kernel_launch(void* const* d_in, const int* in_sizes, int n_in,
                              void* d_out, int out_size)
{
    (void)in_sizes; (void)n_in; (void)out_size;
    const float* x     = (const float*)d_in[0];
    const float* w_qkv = (const float*)d_in[1];
    const float* w_out = (const float*)d_in[2];
    const float* b_out = (const float*)d_in[3];
    float* out = (float*)d_out;

    __half *qkv_p, *ctxT_p, *M_p, *W2_p, *xh_p, *wq_p, *wo_p;
    cudaGetSymbolAddress((void**)&qkv_p,  g_qkvh);
    cudaGetSymbolAddress((void**)&ctxT_p, g_ctxTh);
    cudaGetSymbolAddress((void**)&M_p,    g_M);
    cudaGetSymbolAddress((void**)&W2_p,   g_W2);
    cudaGetSymbolAddress((void**)&xh_p,   g_xh);
    cudaGetSymbolAddress((void**)&wq_p,   g_wqh);
    cudaGetSymbolAddress((void**)&wo_p,   g_woh);

    cudaFuncSetAttribute((const void*)gemm_nn<true>,
                         cudaFuncAttributeMaxDynamicSharedMemorySize, SMEM_NN);
    cudaFuncSetAttribute((const void*)gemm_nn<false>,
                         cudaFuncAttributeMaxDynamicSharedMemorySize, SMEM_NN);
    cudaFuncSetAttribute((const void*)gemm_nt_ctx,
                         cudaFuncAttributeMaxDynamicSharedMemorySize, SMEM_NT);

    dim3 blk(256);

    f2h<<<(BDIM * CIN * NPIX / 4 + 255) / 256, blk>>>(x, xh_p, BDIM * CIN * NPIX / 4);
    const int na4 = QKVR * CIN / 4, nb4 = CIN * HID / 4;
    f2h2<<<(na4 + nb4 + 255) / 256, blk>>>(w_qkv, wq_p, na4, w_out, wo_p, nb4);

    // GEMM1 (k,v only): qkv[b][512:1536] = w_qkv[512:1536] @ x[b]  -> fp16
    gemm_nn<true><<<dim3(NPIX / 128, (QKVR - HID) / 128, BDIM), blk, SMEM_NN>>>(
        wq_p + (long long)HID * CIN, 0, 0, CIN,
        xh_p, (long long)CIN * NPIX, 0,
        qkv_p + (long long)HID * NPIX, (long long)QKVR * NPIX, 0, NPIX,
        nullptr, 1, NPIX, CIN);

    softmax_k<<<BDIM * HEADS * DIMH, blk>>>();

    gemm_nt_ctx<<<dim3(KSPLIT, BDIM * HEADS), blk, SMEM_NT>>>();
    reduce_ctx<<<(BDIM * HEADS * DIMH * DIMH) / 256, blk>>>();

    // M-GEMM: M[b,h](256x128) = w_out[:, h*128:(h+1)*128] @ ctxT[b,h]
    gemm_nn<true><<<dim3(1, CIN / 128, BDIM * HEADS), blk, SMEM_NN>>>(
        wo_p, 0, DIMH, HID,
        ctxT_p, (long long)HEADS * DIMH * DIMH, (long long)DIMH * DIMH,
        M_p, (long long)CIN * HID, DIMH, HID,
        nullptr, HEADS, DIMH, DIMH);

    // W2-GEMM: W2[b](256x256) = Mcat[b](256x512) @ w_q(512x256)
    gemm_nn<true><<<dim3(CIN / 128, CIN / 128, BDIM), blk, SMEM_NN>>>(
        M_p, (long long)CIN * HID, 0, HID,
        wq_p, 0, 0,
        W2_p, (long long)CIN * CIN, 0, CIN,
        nullptr, 1, CIN, HID);

    // Final: out[b] = W2[b](256x256) @ x_h[b](256x4096) + bias  -> fp32
    gemm_nn<false><<<dim3(NPIX / 128, CIN / 128, BDIM), blk, SMEM_NN>>>(
        W2_p, (long long)CIN * CIN, 0, CIN,
        xh_p, (long long)CIN * NPIX, 0,
        out, (long long)CIN * NPIX, 0, NPIX,
        b_out, 1, NPIX, CIN);
}

// round 16
// speedup vs baseline: 1.9524x; 1.0368x over previous
#include <cuda_runtime.h>
#include <cuda_fp16.h>
#include <cstdint>

// ---------------------------------------------------------------------------
// LinearAttention, fp16 mma.sync m16n8k16 (fp32 accum) + ldmatrix + cp.async.
// R16: triple associativity — v is never materialized.
//   k = w_k @ x; k_sm = softmax(k)
//   Z[b,h] = x @ k_sm^T            (NT split-K)
//   P[h]   = w_out[:,h] @ w_v[h]   (batch-independent)
//   U[b,h] = P[h] @ Z[b,h];  W2[b] = Ucat[b] @ w_q;  out = W2 @ x + bias
// ---------------------------------------------------------------------------

#define BDIM   8
#define CIN    256
#define NPIX   4096
#define HEADS  4
#define DIMH   128
#define HID    512
#define QKVR   1536
#define KSPLIT 8

#define SAH    40                 // A smem stride (halfs): 80B
#define SBH    136                // B smem stride (halfs): 272B
#define ASTGH  (128 * SAH)        // 5120 halfs
#define BSTGH  (32 * SBH)         // 4352 halfs
#define SMEM_NN (3 * (ASTGH + BSTGH) * 2)   // 56832
#define SMEM_NT (3 * 2 * ASTGH * 2)         // 61440

__device__ __half g_kh [BDIM][HID][NPIX];                  // k (then k_sm)
__device__ float  g_Zpart[KSPLIT][BDIM * HEADS][CIN][DIMH];// Z split-K partials
__device__ __half g_Zh [BDIM * HEADS][CIN][DIMH];          // Z fp16
__device__ __half g_Ph [HEADS][CIN][CIN];                  // P[h]
__device__ __half g_U  [BDIM][CIN][HID];                   // Ucat
__device__ __half g_W2 [BDIM][CIN][CIN];
__device__ __half g_xh [(size_t)BDIM * CIN * NPIX];
__device__ __half g_wqh[QKVR * CIN];
__device__ __half g_woh[CIN * HID];

// ---------------- helpers ----------------
__device__ __forceinline__ void cpa16(uint32_t d, const void* s) {
    asm volatile("cp.async.cg.shared.global [%0], [%1], 16;\n" :: "r"(d), "l"(s));
}
__device__ __forceinline__ void cp_commit() { asm volatile("cp.async.commit_group;\n"); }
template<int N> __device__ __forceinline__ void cp_wait() {
    asm volatile("cp.async.wait_group %0;\n" :: "n"(N));
}
__device__ __forceinline__ void ldsm_x4(uint32_t r[4], uint32_t a) {
    asm volatile("ldmatrix.sync.aligned.m8n8.x4.shared.b16 {%0,%1,%2,%3}, [%4];"
        : "=r"(r[0]), "=r"(r[1]), "=r"(r[2]), "=r"(r[3]) : "r"(a));
}
__device__ __forceinline__ void ldsm_x4t(uint32_t r[4], uint32_t a) {
    asm volatile("ldmatrix.sync.aligned.m8n8.x4.trans.shared.b16 {%0,%1,%2,%3}, [%4];"
        : "=r"(r[0]), "=r"(r[1]), "=r"(r[2]), "=r"(r[3]) : "r"(a));
}
__device__ __forceinline__ void mma16(float c[4], const uint32_t a[4], const uint32_t b0, const uint32_t b1) {
    asm volatile(
        "mma.sync.aligned.m16n8k16.row.col.f32.f16.f16.f32 "
        "{%0,%1,%2,%3}, {%4,%5,%6,%7}, {%8,%9}, {%0,%1,%2,%3};"
        : "+f"(c[0]), "+f"(c[1]), "+f"(c[2]), "+f"(c[3])
        : "r"(a[0]), "r"(a[1]), "r"(a[2]), "r"(a[3]), "r"(b0), "r"(b1));
}

// ---------------------------------------------------------------------------
__global__ __launch_bounds__(256) void f2h(
    const float* __restrict__ in, __half* __restrict__ out, int n4)
{
    int i = blockIdx.x * 256 + threadIdx.x;
    if (i < n4) {
        float4 v = ((const float4*)in)[i];
        __half2 h0 = __floats2half2_rn(v.x, v.y);
        __half2 h1 = __floats2half2_rn(v.z, v.w);
        uint2 u;
        u.x = *(uint32_t*)&h0;
        u.y = *(uint32_t*)&h1;
        ((uint2*)out)[i] = u;
    }
}
__global__ __launch_bounds__(256) void f2h2(
    const float* __restrict__ a, __half* __restrict__ oa, int na4,
    const float* __restrict__ b, __half* __restrict__ ob, int nb4)
{
    int i = blockIdx.x * 256 + threadIdx.x;
    const float* src; __half* dst; int j;
    if (i < na4) { src = a; dst = oa; j = i; }
    else         { j = i - na4; if (j >= nb4) return; src = b; dst = ob; }
    float4 v = ((const float4*)src)[j];
    __half2 h0 = __floats2half2_rn(v.x, v.y);
    __half2 h1 = __floats2half2_rn(v.z, v.w);
    uint2 u;
    u.x = *(uint32_t*)&h0;
    u.y = *(uint32_t*)&h1;
    ((uint2*)dst)[j] = u;
}

// ---------------------------------------------------------------------------
// NN GEMM fp16: C = A[M,K]@B[K,N] (+bias). 128x128 tile, BK=32, 3-stage.
// B row stride = N; C row stride = ldc.
// ---------------------------------------------------------------------------
template<bool HALF_OUT>
__global__ __launch_bounds__(256, 2) void gemm_nn(
    const __half* __restrict__ A, long long sA1, long long sA2, int lda,
    const __half* __restrict__ B, long long sB1, long long sB2,
    void*         __restrict__ Cv, long long sC1, long long sC2, int ldc,
    const float* __restrict__ bias,
    int zdiv, int N, int K)
{
    extern __shared__ __half sm[];
    __half* Asm = sm;                 // [3][128][SAH]
    __half* Bsm = sm + 3 * ASTGH;     // [3][32][SBH]

    const int bm = blockIdx.y, bn = blockIdx.x;
    const int zo = blockIdx.z / zdiv, zi = blockIdx.z % zdiv;
    A += zo * sA1 + zi * sA2;
    B += zo * sB1 + zi * sB2;

    const int tid  = threadIdx.x;
    const int lane = tid & 31, warp = tid >> 5;
    const int g    = lane >> 2, t4 = lane & 3;
    const int wm   = warp & 3,  wn = warp >> 2;
    const int l15  = lane & 15, lh = lane >> 4;

    const __half* Ag = A + (long long)bm * 128 * lda;
    const __half* Bg = B + bn * 128;

    const uint32_t asm0 = (uint32_t)__cvta_generic_to_shared(Asm);
    const uint32_t bsm0 = (uint32_t)__cvta_generic_to_shared(Bsm);

#define LD_NN(st, kk) do {                                                       \
    uint32_t ab = asm0 + (uint32_t)(st) * (ASTGH * 2);                           \
    uint32_t bb = bsm0 + (uint32_t)(st) * (BSTGH * 2);                           \
    _Pragma("unroll")                                                            \
    for (int t = 0; t < 2; t++) {                                                \
        int idx = t * 256 + tid;                                                 \
        int row = idx >> 2, ch = idx & 3;                                        \
        cpa16(ab + (uint32_t)(row * SAH + ch * 8) * 2,                           \
              Ag + (long long)row * lda + (kk) + ch * 8);                        \
        int kr = idx >> 4, nc = idx & 15;                                        \
        cpa16(bb + (uint32_t)(kr * SBH + nc * 8) * 2,                            \
              Bg + (long long)((kk) + kr) * N + nc * 8);                         \
    }                                                                            \
    cp_commit();                                                                 \
} while (0)

    float acc[2][8][4] = {};
    const int niter = K >> 5;

    LD_NN(0, 0);
    LD_NN(1, 32);

    for (int it = 0; it < niter; ++it) {
        cp_wait<1>();
        __syncthreads();
        const int ls = it + 2;
        if (ls < niter) { LD_NN(ls % 3, ls * 32); }
        else            { cp_commit(); }

        const uint32_t Asb = asm0 + (uint32_t)(it % 3) * (ASTGH * 2);
        const uint32_t Bsb = bsm0 + (uint32_t)(it % 3) * (BSTGH * 2);

#pragma unroll
        for (int k16 = 0; k16 < 32; k16 += 16) {
            uint32_t af[2][4], bf[8][2];
#pragma unroll
            for (int im = 0; im < 2; im++) {
                int m = wm * 32 + im * 16 + l15;
                ldsm_x4(af[im], Asb + (uint32_t)(m * SAH + k16 + lh * 8) * 2);
            }
#pragma unroll
            for (int pr = 0; pr < 4; pr++) {
                int n0 = wn * 64 + pr * 16;
                uint32_t bq[4];
                ldsm_x4t(bq, Bsb + (uint32_t)((k16 + l15) * SBH + n0 + lh * 8) * 2);
                bf[2 * pr][0] = bq[0]; bf[2 * pr][1] = bq[1];
                bf[2 * pr + 1][0] = bq[2]; bf[2 * pr + 1][1] = bq[3];
            }
#pragma unroll
            for (int im = 0; im < 2; im++)
#pragma unroll
                for (int in = 0; in < 8; in++)
                    mma16(acc[im][in], af[im], bf[in][0], bf[in][1]);
        }
    }
#undef LD_NN

    if (HALF_OUT) {
        __half* C = (__half*)Cv + zo * sC1 + zi * sC2;
#pragma unroll
        for (int im = 0; im < 2; im++) {
            int m0 = bm * 128 + wm * 32 + im * 16 + g;
#pragma unroll
            for (int in = 0; in < 8; in++) {
                int n0 = bn * 128 + wn * 64 + in * 8 + t4 * 2;
                __half2 h0 = __floats2half2_rn(acc[im][in][0], acc[im][in][1]);
                __half2 h1 = __floats2half2_rn(acc[im][in][2], acc[im][in][3]);
                *(__half2*)(C + (long long)m0 * ldc + n0)       = h0;
                *(__half2*)(C + (long long)(m0 + 8) * ldc + n0) = h1;
            }
        }
    } else {
        float* C = (float*)Cv + zo * sC1 + zi * sC2;
#pragma unroll
        for (int im = 0; im < 2; im++) {
            int m0 = bm * 128 + wm * 32 + im * 16 + g;
            float bv0 = bias ? bias[m0]     : 0.f;
            float bv1 = bias ? bias[m0 + 8] : 0.f;
#pragma unroll
            for (int in = 0; in < 8; in++) {
                int n0 = bn * 128 + wn * 64 + in * 8 + t4 * 2;
                *(float2*)(C + (long long)m0 * ldc + n0) =
                    make_float2(acc[im][in][0] + bv0, acc[im][in][1] + bv0);
                *(float2*)(C + (long long)(m0 + 8) * ldc + n0) =
                    make_float2(acc[im][in][2] + bv1, acc[im][in][3] + bv1);
            }
        }
    }
}

// ---------------------------------------------------------------------------
// Z-GEMM (NT, split-K): Zpart[slice][bh][mt*128..][d] = sum_{n slice} x[c,n]k_sm[d,n]
// grid (KSPLIT, 2, 32)
// ---------------------------------------------------------------------------
__global__ __launch_bounds__(256, 2) void gemm_nt_z()
{
    extern __shared__ __half sm[];
    __half* Asm = sm;                 // [3][128][SAH] (x rows)
    __half* Bsm = sm + 3 * ASTGH;     // [3][128][SAH] (k_sm rows)

    const int slice = blockIdx.x;
    const int mt    = blockIdx.y;
    const int bh    = blockIdx.z;
    const int b = bh >> 2, h4 = bh & 3;

    const __half* Ag = g_xh + (long long)b * CIN * NPIX + (long long)mt * 128 * NPIX;
    const __half* Bg = &g_kh[b][h4 * DIMH][0];
    float* C = &g_Zpart[slice][bh][mt * 128][0];

    const int tid  = threadIdx.x;
    const int lane = tid & 31, warp = tid >> 5;
    const int g    = lane >> 2, t4 = lane & 3;
    const int wm   = warp & 3,  wn = warp >> 2;
    const int l15  = lane & 15, lh = lane >> 4;

    const uint32_t asm0 = (uint32_t)__cvta_generic_to_shared(Asm);
    const uint32_t bsm0 = (uint32_t)__cvta_generic_to_shared(Bsm);

#define LD_NT(st, kk) do {                                                       \
    uint32_t ab = asm0 + (uint32_t)(st) * (ASTGH * 2);                           \
    uint32_t bb = bsm0 + (uint32_t)(st) * (ASTGH * 2);                           \
    _Pragma("unroll")                                                            \
    for (int t = 0; t < 2; t++) {                                                \
        int idx = t * 256 + tid;                                                 \
        int row = idx >> 2, ch = idx & 3;                                        \
        uint32_t so = (uint32_t)(row * SAH + ch * 8) * 2;                        \
        cpa16(ab + so, Ag + (long long)row * NPIX + (kk) + ch * 8);              \
        cpa16(bb + so, Bg + (long long)row * NPIX + (kk) + ch * 8);              \
    }                                                                            \
    cp_commit();                                                                 \
} while (0)

    float acc[2][8][4] = {};
    const int kbeg  = slice * (NPIX / KSPLIT);
    const int niter = (NPIX / KSPLIT) >> 5;   // 16

    LD_NT(0, kbeg);
    LD_NT(1, kbeg + 32);

    for (int it = 0; it < niter; ++it) {
        cp_wait<1>();
        __syncthreads();
        const int ls = it + 2;
        if (ls < niter) { LD_NT(ls % 3, kbeg + ls * 32); }
        else            { cp_commit(); }

        const uint32_t Asb = asm0 + (uint32_t)(it % 3) * (ASTGH * 2);
        const uint32_t Bsb = bsm0 + (uint32_t)(it % 3) * (ASTGH * 2);

#pragma unroll
        for (int k16 = 0; k16 < 32; k16 += 16) {
            uint32_t af[2][4], bf[8][2];
#pragma unroll
            for (int im = 0; im < 2; im++) {
                int m = wm * 32 + im * 16 + l15;
                ldsm_x4(af[im], Asb + (uint32_t)(m * SAH + k16 + lh * 8) * 2);
            }
#pragma unroll
            for (int pr = 0; pr < 4; pr++) {
                int d0 = wn * 64 + pr * 16;
                uint32_t bq[4];
                ldsm_x4(bq, Bsb + (uint32_t)((d0 + l15) * SAH + k16 + lh * 8) * 2);
                bf[2 * pr][0] = bq[0]; bf[2 * pr][1] = bq[2];
                bf[2 * pr + 1][0] = bq[1]; bf[2 * pr + 1][1] = bq[3];
            }
#pragma unroll
            for (int im = 0; im < 2; im++)
#pragma unroll
                for (int in = 0; in < 8; in++)
                    mma16(acc[im][in], af[im], bf[in][0], bf[in][1]);
        }
    }
#undef LD_NT

#pragma unroll
    for (int im = 0; im < 2; im++) {
        int m0 = wm * 32 + im * 16 + g;
#pragma unroll
        for (int in = 0; in < 8; in++) {
            int n0 = wn * 64 + in * 8 + t4 * 2;
            *(float2*)(C + m0 * 128 + n0)       = make_float2(acc[im][in][0], acc[im][in][1]);
            *(float2*)(C + (m0 + 8) * 128 + n0) = make_float2(acc[im][in][2], acc[im][in][3]);
        }
    }
}

__global__ __launch_bounds__(256) void reduce_z()
{
    const long long i = (long long)blockIdx.x * 256 + threadIdx.x;
    const long long total = (long long)BDIM * HEADS * CIN * DIMH;
    if (i >= total) return;
    const float* p = &g_Zpart[0][0][0][0];
    float s = 0.f;
#pragma unroll
    for (int k = 0; k < KSPLIT; k++) s += p[(long long)k * total + i];
    (&g_Zh[0][0][0])[i] = __float2half_rn(s);
}

// ---------------------------------------------------------------------------
// Softmax over n (4096) on fp16 k rows (g_kh); register-resident, fp32 math.
// ---------------------------------------------------------------------------
__global__ __launch_bounds__(256) void softmax_k()
{
    const int r = blockIdx.x;            // 0..4095
    const int b = r >> 9;
    const int row = r & 511;
    __half* rp = &g_kh[b][row][0];

    __shared__ float red[8];
    const int tid = threadIdx.x;

    uint4 u0 = ((const uint4*)rp)[tid];
    uint4 u1 = ((const uint4*)rp)[256 + tid];

    float v[16];
    {
        const __half2* h0 = (const __half2*)&u0;
        const __half2* h1 = (const __half2*)&u1;
#pragma unroll
        for (int i = 0; i < 4; i++) {
            float2 f0 = __half22float2(h0[i]);
            float2 f1 = __half22float2(h1[i]);
            v[2 * i] = f0.x; v[2 * i + 1] = f0.y;
            v[8 + 2 * i] = f1.x; v[8 + 2 * i + 1] = f1.y;
        }
    }

    float mx = v[0];
#pragma unroll
    for (int i = 1; i < 16; i++) mx = fmaxf(mx, v[i]);
#pragma unroll
    for (int off = 16; off; off >>= 1) mx = fmaxf(mx, __shfl_xor_sync(0xffffffffu, mx, off));
    if ((tid & 31) == 0) red[tid >> 5] = mx;
    __syncthreads();
    float m = red[0];
#pragma unroll
    for (int i = 1; i < 8; i++) m = fmaxf(m, red[i]);
    __syncthreads();

    float s = 0.f;
#pragma unroll
    for (int i = 0; i < 16; i++) { v[i] = __expf(v[i] - m); s += v[i]; }
#pragma unroll
    for (int off = 16; off; off >>= 1) s += __shfl_xor_sync(0xffffffffu, s, off);
    if ((tid & 31) == 0) red[tid >> 5] = s;
    __syncthreads();
    float tot = 0.f;
#pragma unroll
    for (int i = 0; i < 8; i++) tot += red[i];
    const float inv = 1.f / tot;

    uint4 w0, w1;
    __half2* o0 = (__half2*)&w0;
    __half2* o1 = (__half2*)&w1;
#pragma unroll
    for (int i = 0; i < 4; i++) {
        o0[i] = __floats2half2_rn(v[2 * i] * inv, v[2 * i + 1] * inv);
        o1[i] = __floats2half2_rn(v[8 + 2 * i] * inv, v[8 + 2 * i + 1] * inv);
    }
    ((uint4*)rp)[tid] = w0;
    ((uint4*)rp)[256 + tid] = w1;
}

// ---------------------------------------------------------------------------
extern "C" void kernel_launch(void* const* d_in, const int* in_sizes, int n_in,
                              void* d_out, int out_size)
{
    (void)in_sizes; (void)n_in; (void)out_size;
    const float* x     = (const float*)d_in[0];
    const float* w_qkv = (const float*)d_in[1];
    const float* w_out = (const float*)d_in[2];
    const float* b_out = (const float*)d_in[3];
    float* out = (float*)d_out;

    __half *kh_p, *Zh_p, *Ph_p, *U_p, *W2_p, *xh_p, *wq_p, *wo_p;
    cudaGetSymbolAddress((void**)&kh_p, g_kh);
    cudaGetSymbolAddress((void**)&Zh_p, g_Zh);
    cudaGetSymbolAddress((void**)&Ph_p, g_Ph);
    cudaGetSymbolAddress((void**)&U_p,  g_U);
    cudaGetSymbolAddress((void**)&W2_p, g_W2);
    cudaGetSymbolAddress((void**)&xh_p, g_xh);
    cudaGetSymbolAddress((void**)&wq_p, g_wqh);
    cudaGetSymbolAddress((void**)&wo_p, g_woh);

    cudaFuncSetAttribute((const void*)gemm_nn<true>,
                         cudaFuncAttributeMaxDynamicSharedMemorySize, SMEM_NN);
    cudaFuncSetAttribute((const void*)gemm_nn<false>,
                         cudaFuncAttributeMaxDynamicSharedMemorySize, SMEM_NN);
    cudaFuncSetAttribute((const void*)gemm_nt_z,
                         cudaFuncAttributeMaxDynamicSharedMemorySize, SMEM_NT);

    dim3 blk(256);

    f2h<<<(BDIM * CIN * NPIX / 4 + 255) / 256, blk>>>(x, xh_p, BDIM * CIN * NPIX / 4);
    const int na4 = QKVR * CIN / 4, nb4 = CIN * HID / 4;
    f2h2<<<(na4 + nb4 + 255) / 256, blk>>>(w_qkv, wq_p, na4, w_out, wo_p, nb4);

    // P[h] = w_out[:, h*128:(h+1)*128] @ w_v[h]   (w_v rows = wq rows 1024+h*128)
    gemm_nn<true><<<dim3(CIN / 128, CIN / 128, HEADS), blk, SMEM_NN>>>(
        wo_p, DIMH, 0, HID,
        wq_p + (long long)(2 * HID) * CIN, (long long)DIMH * CIN, 0,
        Ph_p, (long long)CIN * CIN, 0, CIN,
        nullptr, 1, CIN, DIMH);

    // GEMM1 (k only): k[b] = w_k @ x[b]  -> fp16 (w_k rows = wq rows 512..1023)
    gemm_nn<true><<<dim3(NPIX / 128, HID / 128, BDIM), blk, SMEM_NN>>>(
        wq_p + (long long)HID * CIN, 0, 0, CIN,
        xh_p, (long long)CIN * NPIX, 0,
        kh_p, (long long)HID * NPIX, 0, NPIX,
        nullptr, 1, NPIX, CIN);

    softmax_k<<<BDIM * HID, blk>>>();

    // Z[b,h] = x[b] @ k_sm[b,h]^T   (split-K partials + reduce)
    gemm_nt_z<<<dim3(KSPLIT, CIN / 128, BDIM * HEADS), blk, SMEM_NT>>>();
    reduce_z<<<(BDIM * HEADS * CIN * DIMH) / 256, blk>>>();

    // U[b,h](256x128) = P[h] @ Zh[b,h]  -> Ucat[b] col-block h
    gemm_nn<true><<<dim3(1, CIN / 128, BDIM * HEADS), blk, SMEM_NN>>>(
        Ph_p, 0, (long long)CIN * CIN, CIN,
        Zh_p, (long long)HEADS * CIN * DIMH, (long long)CIN * DIMH,
        U_p, (long long)CIN * HID, DIMH, HID,
        nullptr, HEADS, DIMH, CIN);

    // W2[b](256x256) = Ucat[b](256x512) @ w_q(512x256)
    gemm_nn<true><<<dim3(CIN / 128, CIN / 128, BDIM), blk, SMEM_NN>>>(
        U_p, (long long)CIN * HID, 0, HID,
        wq_p, 0, 0,
        W2_p, (long long)CIN * CIN, 0, CIN,
        nullptr, 1, CIN, HID);

    // Final: out[b] = W2[b](256x256) @ x_h[b](256x4096) + bias  -> fp32
    gemm_nn<false><<<dim3(NPIX / 128, CIN / 128, BDIM), blk, SMEM_NN>>>(
        W2_p, (long long)CIN * CIN, 0, CIN,
        xh_p, (long long)CIN * NPIX, 0,
        out, (long long)CIN * NPIX, 0, NPIX,
        b_out, 1, NPIX, CIN);
}

// round 17
// speedup vs baseline: 1.9798x; 1.0140x over previous
#include <cuda_runtime.h>
#include <cuda_fp16.h>
#include <cstdint>

// ---------------------------------------------------------------------------
// LinearAttention, fp16 mma.sync m16n8k16 (fp32 accum) + ldmatrix + cp.async.
// R17: R16 algebra (k -> softmax -> Z=x@k_sm^T -> U=P@Z -> W2=Ucat@wq ->
// out=W2@x+b) with overhead trims: Z split-K 8->4, one fused conversion pass.
// ---------------------------------------------------------------------------

#define BDIM   8
#define CIN    256
#define NPIX   4096
#define HEADS  4
#define DIMH   128
#define HID    512
#define QKVR   1536
#define ZSPLIT 4

#define SAH    40                 // A smem stride (halfs): 80B
#define SBH    136                // B smem stride (halfs): 272B
#define ASTGH  (128 * SAH)        // 5120 halfs
#define BSTGH  (32 * SBH)         // 4352 halfs
#define SMEM_NN (3 * (ASTGH + BSTGH) * 2)   // 56832
#define SMEM_NT (3 * 2 * ASTGH * 2)         // 61440

__device__ __half g_kh [BDIM][HID][NPIX];                   // k (then k_sm)
__device__ float  g_Zpart[ZSPLIT][BDIM * HEADS][CIN][DIMH]; // Z split-K partials
__device__ __half g_Zh [BDIM * HEADS][CIN][DIMH];           // Z fp16
__device__ __half g_Ph [HEADS][CIN][CIN];                   // P[h]
__device__ __half g_U  [BDIM][CIN][HID];                    // Ucat
__device__ __half g_W2 [BDIM][CIN][CIN];
__device__ __half g_xh [(size_t)BDIM * CIN * NPIX];
__device__ __half g_wqh[QKVR * CIN];
__device__ __half g_woh[CIN * HID];

// ---------------- helpers ----------------
__device__ __forceinline__ void cpa16(uint32_t d, const void* s) {
    asm volatile("cp.async.cg.shared.global [%0], [%1], 16;\n" :: "r"(d), "l"(s));
}
__device__ __forceinline__ void cp_commit() { asm volatile("cp.async.commit_group;\n"); }
template<int N> __device__ __forceinline__ void cp_wait() {
    asm volatile("cp.async.wait_group %0;\n" :: "n"(N));
}
__device__ __forceinline__ void ldsm_x4(uint32_t r[4], uint32_t a) {
    asm volatile("ldmatrix.sync.aligned.m8n8.x4.shared.b16 {%0,%1,%2,%3}, [%4];"
        : "=r"(r[0]), "=r"(r[1]), "=r"(r[2]), "=r"(r[3]) : "r"(a));
}
__device__ __forceinline__ void ldsm_x4t(uint32_t r[4], uint32_t a) {
    asm volatile("ldmatrix.sync.aligned.m8n8.x4.trans.shared.b16 {%0,%1,%2,%3}, [%4];"
        : "=r"(r[0]), "=r"(r[1]), "=r"(r[2]), "=r"(r[3]) : "r"(a));
}
__device__ __forceinline__ void mma16(float c[4], const uint32_t a[4], const uint32_t b0, const uint32_t b1) {
    asm volatile(
        "mma.sync.aligned.m16n8k16.row.col.f32.f16.f16.f32 "
        "{%0,%1,%2,%3}, {%4,%5,%6,%7}, {%8,%9}, {%0,%1,%2,%3};"
        : "+f"(c[0]), "+f"(c[1]), "+f"(c[2]), "+f"(c[3])
        : "r"(a[0]), "r"(a[1]), "r"(a[2]), "r"(a[3]), "r"(b0), "r"(b1));
}

// ---------------------------------------------------------------------------
// Fused fp32->fp16 conversion: x, w_qkv, w_out in ONE launch.
// ---------------------------------------------------------------------------
__global__ __launch_bounds__(256) void f2h_all(
    const float* __restrict__ x,  __half* __restrict__ ox, int nx4,
    const float* __restrict__ a,  __half* __restrict__ oa, int na4,
    const float* __restrict__ b,  __half* __restrict__ ob, int nb4)
{
    int i = blockIdx.x * 256 + threadIdx.x;
    const float* src; __half* dst; int j;
    if (i < nx4)            { src = x; dst = ox; j = i; }
    else if ((j = i - nx4) < na4) { src = a; dst = oa; }
    else                    { j -= na4; if (j >= nb4) return; src = b; dst = ob; }
    float4 v = ((const float4*)src)[j];
    __half2 h0 = __floats2half2_rn(v.x, v.y);
    __half2 h1 = __floats2half2_rn(v.z, v.w);
    uint2 u;
    u.x = *(uint32_t*)&h0;
    u.y = *(uint32_t*)&h1;
    ((uint2*)dst)[j] = u;
}

// ---------------------------------------------------------------------------
// NN GEMM fp16: C = A[M,K]@B[K,N] (+bias). 128x128 tile, BK=32, 3-stage.
// B row stride = N; C row stride = ldc.
// ---------------------------------------------------------------------------
template<bool HALF_OUT>
__global__ __launch_bounds__(256, 2) void gemm_nn(
    const __half* __restrict__ A, long long sA1, long long sA2, int lda,
    const __half* __restrict__ B, long long sB1, long long sB2,
    void*         __restrict__ Cv, long long sC1, long long sC2, int ldc,
    const float* __restrict__ bias,
    int zdiv, int N, int K)
{
    extern __shared__ __half sm[];
    __half* Asm = sm;                 // [3][128][SAH]
    __half* Bsm = sm + 3 * ASTGH;     // [3][32][SBH]

    const int bm = blockIdx.y, bn = blockIdx.x;
    const int zo = blockIdx.z / zdiv, zi = blockIdx.z % zdiv;
    A += zo * sA1 + zi * sA2;
    B += zo * sB1 + zi * sB2;

    const int tid  = threadIdx.x;
    const int lane = tid & 31, warp = tid >> 5;
    const int g    = lane >> 2, t4 = lane & 3;
    const int wm   = warp & 3,  wn = warp >> 2;
    const int l15  = lane & 15, lh = lane >> 4;

    const __half* Ag = A + (long long)bm * 128 * lda;
    const __half* Bg = B + bn * 128;

    const uint32_t asm0 = (uint32_t)__cvta_generic_to_shared(Asm);
    const uint32_t bsm0 = (uint32_t)__cvta_generic_to_shared(Bsm);

#define LD_NN(st, kk) do {                                                       \
    uint32_t ab = asm0 + (uint32_t)(st) * (ASTGH * 2);                           \
    uint32_t bb = bsm0 + (uint32_t)(st) * (BSTGH * 2);                           \
    _Pragma("unroll")                                                            \
    for (int t = 0; t < 2; t++) {                                                \
        int idx = t * 256 + tid;                                                 \
        int row = idx >> 2, ch = idx & 3;                                        \
        cpa16(ab + (uint32_t)(row * SAH + ch * 8) * 2,                           \
              Ag + (long long)row * lda + (kk) + ch * 8);                        \
        int kr = idx >> 4, nc = idx & 15;                                        \
        cpa16(bb + (uint32_t)(kr * SBH + nc * 8) * 2,                            \
              Bg + (long long)((kk) + kr) * N + nc * 8);                         \
    }                                                                            \
    cp_commit();                                                                 \
} while (0)

    float acc[2][8][4] = {};
    const int niter = K >> 5;

    LD_NN(0, 0);
    LD_NN(1, 32);

    for (int it = 0; it < niter; ++it) {
        cp_wait<1>();
        __syncthreads();
        const int ls = it + 2;
        if (ls < niter) { LD_NN(ls % 3, ls * 32); }
        else            { cp_commit(); }

        const uint32_t Asb = asm0 + (uint32_t)(it % 3) * (ASTGH * 2);
        const uint32_t Bsb = bsm0 + (uint32_t)(it % 3) * (BSTGH * 2);

#pragma unroll
        for (int k16 = 0; k16 < 32; k16 += 16) {
            uint32_t af[2][4], bf[8][2];
#pragma unroll
            for (int im = 0; im < 2; im++) {
                int m = wm * 32 + im * 16 + l15;
                ldsm_x4(af[im], Asb + (uint32_t)(m * SAH + k16 + lh * 8) * 2);
            }
#pragma unroll
            for (int pr = 0; pr < 4; pr++) {
                int n0 = wn * 64 + pr * 16;
                uint32_t bq[4];
                ldsm_x4t(bq, Bsb + (uint32_t)((k16 + l15) * SBH + n0 + lh * 8) * 2);
                bf[2 * pr][0] = bq[0]; bf[2 * pr][1] = bq[1];
                bf[2 * pr + 1][0] = bq[2]; bf[2 * pr + 1][1] = bq[3];
            }
#pragma unroll
            for (int im = 0; im < 2; im++)
#pragma unroll
                for (int in = 0; in < 8; in++)
                    mma16(acc[im][in], af[im], bf[in][0], bf[in][1]);
        }
    }
#undef LD_NN

    if (HALF_OUT) {
        __half* C = (__half*)Cv + zo * sC1 + zi * sC2;
#pragma unroll
        for (int im = 0; im < 2; im++) {
            int m0 = bm * 128 + wm * 32 + im * 16 + g;
#pragma unroll
            for (int in = 0; in < 8; in++) {
                int n0 = bn * 128 + wn * 64 + in * 8 + t4 * 2;
                __half2 h0 = __floats2half2_rn(acc[im][in][0], acc[im][in][1]);
                __half2 h1 = __floats2half2_rn(acc[im][in][2], acc[im][in][3]);
                *(__half2*)(C + (long long)m0 * ldc + n0)       = h0;
                *(__half2*)(C + (long long)(m0 + 8) * ldc + n0) = h1;
            }
        }
    } else {
        float* C = (float*)Cv + zo * sC1 + zi * sC2;
#pragma unroll
        for (int im = 0; im < 2; im++) {
            int m0 = bm * 128 + wm * 32 + im * 16 + g;
            float bv0 = bias ? bias[m0]     : 0.f;
            float bv1 = bias ? bias[m0 + 8] : 0.f;
#pragma unroll
            for (int in = 0; in < 8; in++) {
                int n0 = bn * 128 + wn * 64 + in * 8 + t4 * 2;
                *(float2*)(C + (long long)m0 * ldc + n0) =
                    make_float2(acc[im][in][0] + bv0, acc[im][in][1] + bv0);
                *(float2*)(C + (long long)(m0 + 8) * ldc + n0) =
                    make_float2(acc[im][in][2] + bv1, acc[im][in][3] + bv1);
            }
        }
    }
}

// ---------------------------------------------------------------------------
// Z-GEMM (NT, split-K 4): Zpart[slice][bh][mt*128..][d] += x[c,n] k_sm[d,n]
// grid (ZSPLIT, 2, 32)
// ---------------------------------------------------------------------------
__global__ __launch_bounds__(256, 2) void gemm_nt_z()
{
    extern __shared__ __half sm[];
    __half* Asm = sm;                 // [3][128][SAH] (x rows)
    __half* Bsm = sm + 3 * ASTGH;     // [3][128][SAH] (k_sm rows)

    const int slice = blockIdx.x;
    const int mt    = blockIdx.y;
    const int bh    = blockIdx.z;
    const int b = bh >> 2, h4 = bh & 3;

    const __half* Ag = g_xh + (long long)b * CIN * NPIX + (long long)mt * 128 * NPIX;
    const __half* Bg = &g_kh[b][h4 * DIMH][0];
    float* C = &g_Zpart[slice][bh][mt * 128][0];

    const int tid  = threadIdx.x;
    const int lane = tid & 31, warp = tid >> 5;
    const int g    = lane >> 2, t4 = lane & 3;
    const int wm   = warp & 3,  wn = warp >> 2;
    const int l15  = lane & 15, lh = lane >> 4;

    const uint32_t asm0 = (uint32_t)__cvta_generic_to_shared(Asm);
    const uint32_t bsm0 = (uint32_t)__cvta_generic_to_shared(Bsm);

#define LD_NT(st, kk) do {                                                       \
    uint32_t ab = asm0 + (uint32_t)(st) * (ASTGH * 2);                           \
    uint32_t bb = bsm0 + (uint32_t)(st) * (ASTGH * 2);                           \
    _Pragma("unroll")                                                            \
    for (int t = 0; t < 2; t++) {                                                \
        int idx = t * 256 + tid;                                                 \
        int row = idx >> 2, ch = idx & 3;                                        \
        uint32_t so = (uint32_t)(row * SAH + ch * 8) * 2;                        \
        cpa16(ab + so, Ag + (long long)row * NPIX + (kk) + ch * 8);              \
        cpa16(bb + so, Bg + (long long)row * NPIX + (kk) + ch * 8);              \
    }                                                                            \
    cp_commit();                                                                 \
} while (0)

    float acc[2][8][4] = {};
    const int kbeg  = slice * (NPIX / ZSPLIT);
    const int niter = (NPIX / ZSPLIT) >> 5;   // 32

    LD_NT(0, kbeg);
    LD_NT(1, kbeg + 32);

    for (int it = 0; it < niter; ++it) {
        cp_wait<1>();
        __syncthreads();
        const int ls = it + 2;
        if (ls < niter) { LD_NT(ls % 3, kbeg + ls * 32); }
        else            { cp_commit(); }

        const uint32_t Asb = asm0 + (uint32_t)(it % 3) * (ASTGH * 2);
        const uint32_t Bsb = bsm0 + (uint32_t)(it % 3) * (ASTGH * 2);

#pragma unroll
        for (int k16 = 0; k16 < 32; k16 += 16) {
            uint32_t af[2][4], bf[8][2];
#pragma unroll
            for (int im = 0; im < 2; im++) {
                int m = wm * 32 + im * 16 + l15;
                ldsm_x4(af[im], Asb + (uint32_t)(m * SAH + k16 + lh * 8) * 2);
            }
#pragma unroll
            for (int pr = 0; pr < 4; pr++) {
                int d0 = wn * 64 + pr * 16;
                uint32_t bq[4];
                ldsm_x4(bq, Bsb + (uint32_t)((d0 + l15) * SAH + k16 + lh * 8) * 2);
                bf[2 * pr][0] = bq[0]; bf[2 * pr][1] = bq[2];
                bf[2 * pr + 1][0] = bq[1]; bf[2 * pr + 1][1] = bq[3];
            }
#pragma unroll
            for (int im = 0; im < 2; im++)
#pragma unroll
                for (int in = 0; in < 8; in++)
                    mma16(acc[im][in], af[im], bf[in][0], bf[in][1]);
        }
    }
#undef LD_NT

#pragma unroll
    for (int im = 0; im < 2; im++) {
        int m0 = wm * 32 + im * 16 + g;
#pragma unroll
        for (int in = 0; in < 8; in++) {
            int n0 = wn * 64 + in * 8 + t4 * 2;
            *(float2*)(C + m0 * 128 + n0)       = make_float2(acc[im][in][0], acc[im][in][1]);
            *(float2*)(C + (m0 + 8) * 128 + n0) = make_float2(acc[im][in][2], acc[im][in][3]);
        }
    }
}

__global__ __launch_bounds__(256) void reduce_z()
{
    const long long i = (long long)blockIdx.x * 256 + threadIdx.x;
    const long long total = (long long)BDIM * HEADS * CIN * DIMH;
    if (i >= total) return;
    const float* p = &g_Zpart[0][0][0][0];
    float s = 0.f;
#pragma unroll
    for (int k = 0; k < ZSPLIT; k++) s += p[(long long)k * total + i];
    (&g_Zh[0][0][0])[i] = __float2half_rn(s);
}

// ---------------------------------------------------------------------------
// Softmax over n (4096) on fp16 k rows (g_kh); register-resident, fp32 math.
// ---------------------------------------------------------------------------
__global__ __launch_bounds__(256) void softmax_k()
{
    const int r = blockIdx.x;            // 0..4095
    const int b = r >> 9;
    const int row = r & 511;
    __half* rp = &g_kh[b][row][0];

    __shared__ float red[8];
    const int tid = threadIdx.x;

    uint4 u0 = ((const uint4*)rp)[tid];
    uint4 u1 = ((const uint4*)rp)[256 + tid];

    float v[16];
    {
        const __half2* h0 = (const __half2*)&u0;
        const __half2* h1 = (const __half2*)&u1;
#pragma unroll
        for (int i = 0; i < 4; i++) {
            float2 f0 = __half22float2(h0[i]);
            float2 f1 = __half22float2(h1[i]);
            v[2 * i] = f0.x; v[2 * i + 1] = f0.y;
            v[8 + 2 * i] = f1.x; v[8 + 2 * i + 1] = f1.y;
        }
    }

    float mx = v[0];
#pragma unroll
    for (int i = 1; i < 16; i++) mx = fmaxf(mx, v[i]);
#pragma unroll
    for (int off = 16; off; off >>= 1) mx = fmaxf(mx, __shfl_xor_sync(0xffffffffu, mx, off));
    if ((tid & 31) == 0) red[tid >> 5] = mx;
    __syncthreads();
    float m = red[0];
#pragma unroll
    for (int i = 1; i < 8; i++) m = fmaxf(m, red[i]);
    __syncthreads();

    float s = 0.f;
#pragma unroll
    for (int i = 0; i < 16; i++) { v[i] = __expf(v[i] - m); s += v[i]; }
#pragma unroll
    for (int off = 16; off; off >>= 1) s += __shfl_xor_sync(0xffffffffu, s, off);
    if ((tid & 31) == 0) red[tid >> 5] = s;
    __syncthreads();
    float tot = 0.f;
#pragma unroll
    for (int i = 0; i < 8; i++) tot += red[i];
    const float inv = 1.f / tot;

    uint4 w0, w1;
    __half2* o0 = (__half2*)&w0;
    __half2* o1 = (__half2*)&w1;
#pragma unroll
    for (int i = 0; i < 4; i++) {
        o0[i] = __floats2half2_rn(v[2 * i] * inv, v[2 * i + 1] * inv);
        o1[i] = __floats2half2_rn(v[8 + 2 * i] * inv, v[8 + 2 * i + 1] * inv);
    }
    ((uint4*)rp)[tid] = w0;
    ((uint4*)rp)[256 + tid] = w1;
}

// ---------------------------------------------------------------------------
extern "C" void kernel_launch(void* const* d_in, const int* in_sizes, int n_in,
                              void* d_out, int out_size)
{
    (void)in_sizes; (void)n_in; (void)out_size;
    const float* x     = (const float*)d_in[0];
    const float* w_qkv = (const float*)d_in[1];
    const float* w_out = (const float*)d_in[2];
    const float* b_out = (const float*)d_in[3];
    float* out = (float*)d_out;

    __half *kh_p, *Zh_p, *Ph_p, *U_p, *W2_p, *xh_p, *wq_p, *wo_p;
    cudaGetSymbolAddress((void**)&kh_p, g_kh);
    cudaGetSymbolAddress((void**)&Zh_p, g_Zh);
    cudaGetSymbolAddress((void**)&Ph_p, g_Ph);
    cudaGetSymbolAddress((void**)&U_p,  g_U);
    cudaGetSymbolAddress((void**)&W2_p, g_W2);
    cudaGetSymbolAddress((void**)&xh_p, g_xh);
    cudaGetSymbolAddress((void**)&wq_p, g_wqh);
    cudaGetSymbolAddress((void**)&wo_p, g_woh);

    cudaFuncSetAttribute((const void*)gemm_nn<true>,
                         cudaFuncAttributeMaxDynamicSharedMemorySize, SMEM_NN);
    cudaFuncSetAttribute((const void*)gemm_nn<false>,
                         cudaFuncAttributeMaxDynamicSharedMemorySize, SMEM_NN);
    cudaFuncSetAttribute((const void*)gemm_nt_z,
                         cudaFuncAttributeMaxDynamicSharedMemorySize, SMEM_NT);

    dim3 blk(256);

    // ONE conversion pass: x, w_qkv, w_out -> fp16
    const int nx4 = BDIM * CIN * NPIX / 4;
    const int na4 = QKVR * CIN / 4, nb4 = CIN * HID / 4;
    f2h_all<<<(nx4 + na4 + nb4 + 255) / 256, blk>>>(
        x, xh_p, nx4, w_qkv, wq_p, na4, w_out, wo_p, nb4);

    // P[h] = w_out[:, h*128:(h+1)*128] @ w_v[h]
    gemm_nn<true><<<dim3(CIN / 128, CIN / 128, HEADS), blk, SMEM_NN>>>(
        wo_p, DIMH, 0, HID,
        wq_p + (long long)(2 * HID) * CIN, (long long)DIMH * CIN, 0,
        Ph_p, (long long)CIN * CIN, 0, CIN,
        nullptr, 1, CIN, DIMH);

    // k[b] = w_k @ x[b]  -> fp16
    gemm_nn<true><<<dim3(NPIX / 128, HID / 128, BDIM), blk, SMEM_NN>>>(
        wq_p + (long long)HID * CIN, 0, 0, CIN,
        xh_p, (long long)CIN * NPIX, 0,
        kh_p, (long long)HID * NPIX, 0, NPIX,
        nullptr, 1, NPIX, CIN);

    softmax_k<<<BDIM * HID, blk>>>();

    // Z[b,h] = x[b] @ k_sm[b,h]^T   (split-K 4 + reduce)
    gemm_nt_z<<<dim3(ZSPLIT, CIN / 128, BDIM * HEADS), blk, SMEM_NT>>>();
    reduce_z<<<(BDIM * HEADS * CIN * DIMH) / 256, blk>>>();

    // U[b,h](256x128) = P[h] @ Zh[b,h]  -> Ucat[b] col-block h
    gemm_nn<true><<<dim3(1, CIN / 128, BDIM * HEADS), blk, SMEM_NN>>>(
        Ph_p, 0, (long long)CIN * CIN, CIN,
        Zh_p, (long long)HEADS * CIN * DIMH, (long long)CIN * DIMH,
        U_p, (long long)CIN * HID, DIMH, HID,
        nullptr, HEADS, DIMH, CIN);

    // W2[b](256x256) = Ucat[b](256x512) @ w_q(512x256)
    gemm_nn<true><<<dim3(CIN / 128, CIN / 128, BDIM), blk, SMEM_NN>>>(
        U_p, (long long)CIN * HID, 0, HID,
        wq_p, 0, 0,
        W2_p, (long long)CIN * CIN, 0, CIN,
        nullptr, 1, CIN, HID);

    // Final: out[b] = W2[b](256x256) @ x_h[b](256x4096) + bias  -> fp32
    gemm_nn<false><<<dim3(NPIX / 128, CIN / 128, BDIM), blk, SMEM_NN>>>(
        W2_p, (long long)CIN * CIN, 0, CIN,
        xh_p, (long long)CIN * NPIX, 0,
        out, (long long)CIN * NPIX, 0, NPIX,
        b_out, 1, NPIX, CIN);
}